// round 13
// baseline (speedup 1.0000x reference)
#include <cuda_runtime.h>
#include <cuda_fp16.h>
#include <math.h>
#include <stdint.h>

#define B_  2
#define T_  2048
#define C_  1024
#define H_  16
#define HD_ 64
#define SCALE_ 0.125f
#define BT_ (B_ * T_)

typedef __half hf;
typedef uint32_t u32;

// ---------------- scratch ----------------
__device__ hf g_xh[(size_t)BT_ * C_];
__device__ hf g_xl[(size_t)BT_ * C_];
__device__ hf g_qkvh[(size_t)BT_ * 3 * C_];
__device__ hf g_qkvl[(size_t)BT_ * 3 * C_];
__device__ hf g_ah[(size_t)BT_ * C_];
__device__ hf g_al[(size_t)BT_ * C_];
__device__ hf g_wq[(size_t)3 * C_ * C_];
__device__ hf g_wo[(size_t)C_ * C_];
__device__ float g_bq[(size_t)B_ * H_ * T_];
__device__ float g_kp[(size_t)B_ * H_ * T_];

// ---------------- helpers ----------------
__device__ __forceinline__ u32 smem_u32(const void* p) {
    return (u32)__cvta_generic_to_shared(p);
}
__device__ __forceinline__ void ldsm_x4(u32* r, u32 addr) {
    asm volatile("ldmatrix.sync.aligned.m8n8.x4.shared.b16 {%0,%1,%2,%3}, [%4];"
        : "=r"(r[0]), "=r"(r[1]), "=r"(r[2]), "=r"(r[3]) : "r"(addr));
}
__device__ __forceinline__ void ldsm_x2(u32* r, u32 addr) {
    asm volatile("ldmatrix.sync.aligned.m8n8.x2.shared.b16 {%0,%1}, [%2];"
        : "=r"(r[0]), "=r"(r[1]) : "r"(addr));
}
__device__ __forceinline__ void ldsm_x2t(u32* r, u32 addr) {
    asm volatile("ldmatrix.sync.aligned.m8n8.x2.trans.shared.b16 {%0,%1}, [%2];"
        : "=r"(r[0]), "=r"(r[1]) : "r"(addr));
}
__device__ __forceinline__ void mma_f16(float* c, const u32* a, const u32* b) {
    asm volatile("mma.sync.aligned.m16n8k16.row.col.f32.f16.f16.f32 "
        "{%0,%1,%2,%3}, {%4,%5,%6,%7}, {%8,%9}, {%0,%1,%2,%3};"
        : "+f"(c[0]), "+f"(c[1]), "+f"(c[2]), "+f"(c[3])
        : "r"(a[0]), "r"(a[1]), "r"(a[2]), "r"(a[3]), "r"(b[0]), "r"(b[1]));
}
// fp16-accumulate variant (D,C packed f16x2 in 2 regs)
__device__ __forceinline__ void mma_f16acc(u32* c, const u32* a, const u32* b) {
    asm volatile("mma.sync.aligned.m16n8k16.row.col.f16.f16.f16.f16 "
        "{%0,%1}, {%2,%3,%4,%5}, {%6,%7}, {%0,%1};"
        : "+r"(c[0]), "+r"(c[1])
        : "r"(a[0]), "r"(a[1]), "r"(a[2]), "r"(a[3]), "r"(b[0]), "r"(b[1]));
}
__device__ __forceinline__ void split2h(float a, float b, u32& hi, u32& lo) {
    __half ha = __float2half_rn(a), hb = __float2half_rn(b);
    __half2 H = __halves2half2(ha, hb);
    __half2 L = __halves2half2(__float2half_rn(a - __half2float(ha)),
                               __float2half_rn(b - __half2float(hb)));
    hi = *(u32*)&H;
    lo = *(u32*)&L;
}
__device__ __forceinline__ void cp16(u32 dst, const void* src) {
    asm volatile("cp.async.cg.shared.global [%0], [%1], 16;" :: "r"(dst), "l"(src));
}
#define CP_COMMIT() asm volatile("cp.async.commit_group;" ::: "memory")
#define CP_WAIT(n)  asm volatile("cp.async.wait_group %0;" :: "n"(n) : "memory")

// ---------------------------------------------------------------------------
// split fp32 -> (fp16 hi, fp16 lo)
// ---------------------------------------------------------------------------
__global__ void split_kernel(const float* __restrict__ src,
                             hf* __restrict__ hi, hf* __restrict__ lo, int n4)
{
    int i = blockIdx.x * blockDim.x + threadIdx.x;
    if (i >= n4) return;
    float4 v = ((const float4*)src)[i];
    u32 h0, l0, h1, l1;
    split2h(v.x, v.y, h0, l0);
    split2h(v.z, v.w, h1, l1);
    ((u32*)hi)[2 * i]     = h0;
    ((u32*)hi)[2 * i + 1] = h1;
    ((u32*)lo)[2 * i]     = l0;
    ((u32*)lo)[2 * i + 1] = l1;
}

// convert + transpose: src fp32 [K][N] -> fp16 [N][K]
__global__ void cvt_transpose_kernel(const float* __restrict__ src,
                                     hf* __restrict__ dst, int K, int N)
{
    __shared__ float tile[32][33];
    const int n0 = blockIdx.x * 32, k0 = blockIdx.y * 32;
    const int tx = threadIdx.x, ty = threadIdx.y;
    for (int r = ty; r < 32; r += 8)
        tile[r][tx] = src[(size_t)(k0 + r) * N + n0 + tx];
    __syncthreads();
    for (int r = ty; r < 32; r += 8)
        dst[(size_t)(n0 + r) * K + k0 + tx] = __float2half_rn(tile[tx][r]);
}

// ---------------------------------------------------------------------------
// E8 projections
// ---------------------------------------------------------------------------
__global__ void proj_kernel(const hf* __restrict__ qkvh, const hf* __restrict__ qkvl,
                            const float* __restrict__ head_scales,
                            const float* __restrict__ head_dirs,
                            float* __restrict__ bq, float* __restrict__ kp)
{
    const int i = blockIdx.x * blockDim.x + threadIdx.x;
    if (i >= BT_ * H_) return;
    const int bt = i >> 4;
    const int h  = i & 15;
    const size_t base = (size_t)bt * (3 * C_) + h * HD_;
    float qp = 0.f, kv = 0.f;
    #pragma unroll
    for (int d = 0; d < 8; d++) {
        const float dir = head_dirs[h * 8 + d];
        qp += (__half2float(qkvh[base + d]) + __half2float(qkvl[base + d])) * dir;
        kv += __half2float(qkvh[base + C_ + d]) * dir;
    }
    const int b = bt >> 11;
    const int t = bt & (T_ - 1);
    const size_t idx = (size_t)(b * H_ + h) * T_ + t;
    bq[idx] = head_scales[h] * qp;
    kp[idx] = kv;
}

// ---------------------------------------------------------------------------
// fp16x2 GEMM: hi-plane -> fp32 acc, lo-plane -> fp16 acc (2x rate probe).
// Block 128x128x32, 8 warps (2m x 4n) 64x32 warp tiles. cp.async 3-stage.
// ---------------------------------------------------------------------------
#define BM 128
#define BN 128
#define BK 32
#define SPITCH 40
#define PLANE_BYTES (BM * SPITCH * 2)
#define GSTAGE (3 * PLANE_BYTES)
#define NSTAGES 3
#define GSMEM_TOTAL (NSTAGES * GSTAGE)

template<bool SPLIT>
__global__ __launch_bounds__(256, 1) void gemm_f16x2(
    const hf* __restrict__ Ah, const hf* __restrict__ Al,
    const hf* __restrict__ Bs,
    float* __restrict__ Cm, hf* __restrict__ Ch, hf* __restrict__ Cl,
    int M, int N, int K)
{
    extern __shared__ char gsm[];
    const u32 sb = smem_u32(gsm);

    const int tid  = threadIdx.x;
    const int lane = tid & 31, wid = tid >> 5;
    const int wm = (wid & 1) * 64;
    const int wn = (wid >> 1) * 32;
    const int row0 = blockIdx.y * BM;
    const int col0 = blockIdx.x * BN;

    const int gr = tid >> 1;
    const int gc = (tid & 1) * 16;
    const hf* pAh = Ah + (size_t)(row0 + gr) * K + gc;
    const hf* pAl = Al + (size_t)(row0 + gr) * K + gc;
    const hf* pB  = Bs + (size_t)(col0 + gr) * K + gc;
    const u32 dstoff = (u32)(gr * (SPITCH * 2) + gc * 2);

    float acc[4][4][4];
    u32 accL[4][4][2];   // fp16x2 accumulators for lo-plane
    #pragma unroll
    for (int i = 0; i < 4; i++)
        #pragma unroll
        for (int j = 0; j < 4; j++) {
            #pragma unroll
            for (int k = 0; k < 4; k++) acc[i][j][k] = 0.f;
            accL[i][j][0] = 0u;
            accL[i][j][1] = 0u;
        }

    const int sub = lane >> 3, li = lane & 7;
    const int arow = (sub & 1) * 8 + li;
    const int acol = (sub >> 1) * 8;
    const int brow = lane & 7;
    const int bcol = ((lane >> 3) & 1) * 8;

    const int nk = K / BK;

    #define LOAD_STAGE(ic, s) do { \
        const u32 _b = sb + (s) * GSTAGE + dstoff; \
        const size_t _ko = (size_t)(ic) * BK; \
        cp16(_b,                        pAh + _ko); \
        cp16(_b + 16,                   pAh + _ko + 8); \
        cp16(_b + PLANE_BYTES,          pAl + _ko); \
        cp16(_b + PLANE_BYTES + 16,     pAl + _ko + 8); \
        cp16(_b + 2 * PLANE_BYTES,      pB + _ko); \
        cp16(_b + 2 * PLANE_BYTES + 16, pB + _ko + 8); \
    } while (0)

    LOAD_STAGE(0, 0); CP_COMMIT();
    LOAD_STAGE(1, 1); CP_COMMIT();

    int st = 0;
    for (int ic = 0; ic < nk; ic++) {
        if (ic + 1 < nk) { CP_WAIT(1); } else { CP_WAIT(0); }
        __syncthreads();

        const u32 bAh = sb + st * GSTAGE;
        const u32 bAl = bAh + PLANE_BYTES;
        const u32 bB  = bAh + 2 * PLANE_BYTES;

        if (ic + 2 < nk) {
            int ws = st + 2; if (ws >= NSTAGES) ws -= NSTAGES;
            LOAD_STAGE(ic + 2, ws); CP_COMMIT();
        }

        #pragma unroll
        for (int ks = 0; ks < BK; ks += 16) {
            u32 fB[4][2];
            #pragma unroll
            for (int nf = 0; nf < 4; nf++) {
                u32 off = (u32)(((wn + nf * 8 + brow) * SPITCH + ks + bcol) * 2);
                ldsm_x2(fB[nf], bB + off);
            }
            #pragma unroll
            for (int mf = 0; mf < 4; mf++) {
                u32 off = (u32)(((wm + mf * 16 + arow) * SPITCH + ks + acol) * 2);
                u32 fA[4], fL[4];
                ldsm_x4(fA, bAh + off);
                ldsm_x4(fL, bAl + off);
                #pragma unroll
                for (int nf = 0; nf < 4; nf++) {
                    mma_f16(acc[mf][nf], fA, fB[nf]);       // hi: fp32 acc
                    mma_f16acc(accL[mf][nf], fL, fB[nf]);   // lo: fp16 acc
                }
            }
        }
        if (++st == NSTAGES) st = 0;
    }
    #undef LOAD_STAGE

    const int g = lane >> 2, t4 = lane & 3;
    #pragma unroll
    for (int mf = 0; mf < 4; mf++) {
        #pragma unroll
        for (int nf = 0; nf < 4; nf++) {
            const __half2 L0 = *(const __half2*)&accL[mf][nf][0];
            const __half2 L1 = *(const __half2*)&accL[mf][nf][1];
            const float c0 = acc[mf][nf][0] + __half2float(L0.x);
            const float c1 = acc[mf][nf][1] + __half2float(L0.y);
            const float c2 = acc[mf][nf][2] + __half2float(L1.x);
            const float c3 = acc[mf][nf][3] + __half2float(L1.y);
            const size_t r  = (size_t)(row0 + wm + mf * 16 + g);
            const size_t cc = (size_t)(col0 + wn + nf * 8 + 2 * t4);
            if (!SPLIT) {
                *(float2*)&Cm[r * N + cc]       = make_float2(c0, c1);
                *(float2*)&Cm[(r + 8) * N + cc] = make_float2(c2, c3);
            } else {
                u32 h01, l01, h23, l23;
                split2h(c0, c1, h01, l01);
                split2h(c2, c3, h23, l23);
                *(u32*)&Ch[r * N + cc]       = h01;
                *(u32*)&Cl[r * N + cc]       = l01;
                *(u32*)&Ch[(r + 8) * N + cc] = h23;
                *(u32*)&Cl[(r + 8) * N + cc] = l23;
            }
        }
    }
}

// ---------------------------------------------------------------------------
// fp16x2 flash attention + E8 rank-1 bias (precomputed projections).
// (unchanged from R11/R12 best)
// ---------------------------------------------------------------------------
#define KPITCH 72
#define APL (64 * KPITCH * 2)

__global__ __launch_bounds__(256, 1) void attn_mma(
    const hf* __restrict__ qkvh, const hf* __restrict__ qkvl,
    const float* __restrict__ gbq, const float* __restrict__ gkp,
    hf* __restrict__ atth, hf* __restrict__ attl)
{
    extern __shared__ hf dsm[];
    hf* sQh = dsm;
    hf* sQl = sQh + 128 * KPITCH;
    hf* sKV = sQl + 128 * KPITCH;
    float* skp = (float*)(sKV + 4 * 64 * KPITCH);

    const u32 kvb  = smem_u32(sKV);
    const u32 skpb = smem_u32(skp);

    const int tid  = threadIdx.x;
    const int lane = tid & 31, wid = tid >> 5;
    const int wm   = wid * 16;
    const int bh   = blockIdx.y;
    const int b    = bh >> 4;
    const int h    = bh & 15;
    const int qi   = (int)gridDim.x - 1 - (int)blockIdx.x;
    const int q0   = qi * 128;

    #pragma unroll
    for (int i = tid; i < 128 * 8; i += 256) {
        const int row = i >> 3, seg = (i & 7) * 8;
        const size_t gb = (size_t)(b * T_ + q0 + row) * (3 * C_) + h * HD_ + seg;
        *(int4*)&sQh[row * KPITCH + seg] = *(const int4*)(qkvh + gb);
        *(int4*)&sQl[row * KPITCH + seg] = *(const int4*)(qkvl + gb);
    }

    const int ktmax = 2 * qi + 2;

    #define LOAD_TILE(kt, s) do { \
        const int _k0 = (kt) * 64; \
        const u32 _sb = kvb + (s) * (2 * APL); \
        _Pragma("unroll") \
        for (int _j = 0; _j < 2; _j++) { \
            const int _i = tid + _j * 256; \
            const int _row = _i >> 3, _seg = (_i & 7) * 8; \
            const size_t _gb = (size_t)(b * T_ + _k0 + _row) * (3 * C_) + h * HD_ + _seg; \
            const u32 _d = _sb + (u32)(_row * (KPITCH * 2) + _seg * 2); \
            cp16(_d,       qkvh + _gb + C_); \
            cp16(_d + APL, qkvh + _gb + 2 * C_); \
        } \
        if (tid < 16) \
            cp16(skpb + (s) * 256 + tid * 16, gkp + (size_t)bh * T_ + _k0 + tid * 4); \
    } while (0)

    LOAD_TILE(0, 0); CP_COMMIT();
    __syncthreads();

    const int sub = lane >> 3, li = lane & 7;
    const int arow = (sub & 1) * 8 + li;
    const int acol = (sub >> 1) * 8;
    const u32 baseQh = smem_u32(sQh), baseQl = smem_u32(sQl);
    u32 qfh[4][4], qfl[4][4];
    #pragma unroll
    for (int ks = 0; ks < 4; ks++) {
        u32 off = (u32)(((wm + arow) * KPITCH + ks * 16 + acol) * 2);
        ldsm_x4(qfh[ks], baseQh + off);
        ldsm_x4(qfl[ks], baseQl + off);
    }

    const int g = lane >> 2, t4 = lane & 3;
    const int row_g0 = q0 + wm + g;
    const int row_g1 = row_g0 + 8;
    const float bq0 = gbq[(size_t)bh * T_ + row_g0];
    const float bq1 = gbq[(size_t)bh * T_ + row_g1];

    float m0 = -INFINITY, m1 = -INFINITY, l0 = 0.f, l1 = 0.f;
    float o[8][4];
    #pragma unroll
    for (int j = 0; j < 8; j++)
        #pragma unroll
        for (int e = 0; e < 4; e++) o[j][e] = 0.f;

    const int brow = lane & 7;
    const int bcol = ((lane >> 3) & 1) * 8;
    const int vrow = lane & 15;

    for (int kt = 0; kt < ktmax; kt++) {
        const int s = kt & 1;
        const int k0 = kt * 64;

        CP_WAIT(0);
        __syncthreads();
        if (kt + 1 < ktmax) { LOAD_TILE(kt + 1, 1 - s); CP_COMMIT(); }

        const u32 bK = kvb + s * (2 * APL);
        const u32 bV = bK + APL;
        const float* kp_s = skp + s * 64;

        float s_[8][4];
        #pragma unroll
        for (int j = 0; j < 8; j++)
            #pragma unroll
            for (int e = 0; e < 4; e++) s_[j][e] = 0.f;

        #pragma unroll
        for (int ks = 0; ks < 4; ks++) {
            #pragma unroll
            for (int j = 0; j < 8; j++) {
                u32 kf[2];
                const u32 off = (u32)(((j * 8 + brow) * KPITCH + ks * 16 + bcol) * 2);
                ldsm_x2(kf, bK + off);
                mma_f16(s_[j], qfh[ks], kf);
                mma_f16(s_[j], qfl[ks], kf);
            }
        }

        const bool need_mask = (kt >= 2 * qi);
        #pragma unroll
        for (int j = 0; j < 8; j++) {
            const float2 kp = *(const float2*)&kp_s[j * 8 + 2 * t4];
            s_[j][0] = s_[j][0] * SCALE_ + bq0 * kp.x;
            s_[j][1] = s_[j][1] * SCALE_ + bq0 * kp.y;
            s_[j][2] = s_[j][2] * SCALE_ + bq1 * kp.x;
            s_[j][3] = s_[j][3] * SCALE_ + bq1 * kp.y;
            if (need_mask) {
                const int key0 = k0 + j * 8 + 2 * t4;
                if (key0 > row_g0)     s_[j][0] = -INFINITY;
                if (key0 + 1 > row_g0) s_[j][1] = -INFINITY;
                if (key0 > row_g1)     s_[j][2] = -INFINITY;
                if (key0 + 1 > row_g1) s_[j][3] = -INFINITY;
            }
        }

        float mx0 = s_[0][0], mx1 = s_[0][2];
        #pragma unroll
        for (int j = 0; j < 8; j++) {
            mx0 = fmaxf(mx0, fmaxf(s_[j][0], s_[j][1]));
            mx1 = fmaxf(mx1, fmaxf(s_[j][2], s_[j][3]));
        }
        mx0 = fmaxf(mx0, __shfl_xor_sync(0xffffffffu, mx0, 1));
        mx0 = fmaxf(mx0, __shfl_xor_sync(0xffffffffu, mx0, 2));
        mx1 = fmaxf(mx1, __shfl_xor_sync(0xffffffffu, mx1, 1));
        mx1 = fmaxf(mx1, __shfl_xor_sync(0xffffffffu, mx1, 2));

        const float mn0 = fmaxf(m0, mx0), mn1 = fmaxf(m1, mx1);
        const float a0 = __expf(m0 - mn0), a1 = __expf(m1 - mn1);
        m0 = mn0; m1 = mn1;

        float rs0 = 0.f, rs1 = 0.f;
        #pragma unroll
        for (int j = 0; j < 8; j++) {
            s_[j][0] = __expf(s_[j][0] - m0);
            s_[j][1] = __expf(s_[j][1] - m0);
            s_[j][2] = __expf(s_[j][2] - m1);
            s_[j][3] = __expf(s_[j][3] - m1);
            rs0 += s_[j][0] + s_[j][1];
            rs1 += s_[j][2] + s_[j][3];
        }
        rs0 += __shfl_xor_sync(0xffffffffu, rs0, 1);
        rs0 += __shfl_xor_sync(0xffffffffu, rs0, 2);
        rs1 += __shfl_xor_sync(0xffffffffu, rs1, 1);
        rs1 += __shfl_xor_sync(0xffffffffu, rs1, 2);
        l0 = l0 * a0 + rs0;
        l1 = l1 * a1 + rs1;

        #pragma unroll
        for (int j = 0; j < 8; j++) {
            o[j][0] *= a0; o[j][1] *= a0;
            o[j][2] *= a1; o[j][3] *= a1;
        }

        u32 pah[4][4], pal[4][4];
        #pragma unroll
        for (int s2 = 0; s2 < 4; s2++) {
            split2h(s_[2 * s2][0],     s_[2 * s2][1],     pah[s2][0], pal[s2][0]);
            split2h(s_[2 * s2][2],     s_[2 * s2][3],     pah[s2][1], pal[s2][1]);
            split2h(s_[2 * s2 + 1][0], s_[2 * s2 + 1][1], pah[s2][2], pal[s2][2]);
            split2h(s_[2 * s2 + 1][2], s_[2 * s2 + 1][3], pah[s2][3], pal[s2][3]);
        }

        #pragma unroll
        for (int s2 = 0; s2 < 4; s2++) {
            #pragma unroll
            for (int j = 0; j < 8; j++) {
                u32 vf[2];
                const u32 off = (u32)(((s2 * 16 + vrow) * KPITCH + j * 8) * 2);
                ldsm_x2t(vf, bV + off);
                mma_f16(o[j], pah[s2], vf);
                mma_f16(o[j], pal[s2], vf);
            }
        }
    }
    #undef LOAD_TILE

    const float inv0 = 1.f / l0, inv1 = 1.f / l1;
    #pragma unroll
    for (int j = 0; j < 8; j++) {
        u32 h01, l01, h23, l23;
        split2h(o[j][0] * inv0, o[j][1] * inv0, h01, l01);
        split2h(o[j][2] * inv1, o[j][3] * inv1, h23, l23);
        const size_t r0o = (size_t)(b * T_ + row_g0) * C_ + h * HD_ + j * 8 + 2 * t4;
        const size_t r1o = (size_t)(b * T_ + row_g1) * C_ + h * HD_ + j * 8 + 2 * t4;
        *(u32*)&atth[r0o] = h01;
        *(u32*)&attl[r0o] = l01;
        *(u32*)&atth[r1o] = h23;
        *(u32*)&attl[r1o] = l23;
    }
}

// ---------------------------------------------------------------------------
extern "C" void kernel_launch(void* const* d_in, const int* in_sizes, int n_in,
                              void* d_out, int out_size)
{
    const float* x           = (const float*)d_in[0];
    const float* w_qkv       = (const float*)d_in[1];
    const float* w_out       = (const float*)d_in[2];
    const float* head_scales = (const float*)d_in[3];
    const float* head_dirs   = (const float*)d_in[4];
    float*       out         = (float*)d_out;

    hf *xh, *xl, *qkvh, *qkvl, *ah, *al, *wq, *wo;
    float *bq, *kp;
    cudaGetSymbolAddress((void**)&xh, g_xh);
    cudaGetSymbolAddress((void**)&xl, g_xl);
    cudaGetSymbolAddress((void**)&qkvh, g_qkvh);
    cudaGetSymbolAddress((void**)&qkvl, g_qkvl);
    cudaGetSymbolAddress((void**)&ah, g_ah);
    cudaGetSymbolAddress((void**)&al, g_al);
    cudaGetSymbolAddress((void**)&wq, g_wq);
    cudaGetSymbolAddress((void**)&wo, g_wo);
    cudaGetSymbolAddress((void**)&bq, g_bq);
    cudaGetSymbolAddress((void**)&kp, g_kp);

    const int ATT_SMEM = (128 * 2 + 64 * 4) * KPITCH * (int)sizeof(hf)
                       + 2 * 64 * (int)sizeof(float);
    cudaFuncSetAttribute(attn_mma, cudaFuncAttributeMaxDynamicSharedMemorySize, ATT_SMEM);
    cudaFuncSetAttribute(gemm_f16x2<true>,  cudaFuncAttributeMaxDynamicSharedMemorySize, GSMEM_TOTAL);
    cudaFuncSetAttribute(gemm_f16x2<false>, cudaFuncAttributeMaxDynamicSharedMemorySize, GSMEM_TOTAL);

    // splits / converts
    {
        int n4 = BT_ * C_ / 4;
        split_kernel<<<(n4 + 255) / 256, 256>>>(x, xh, xl, n4);
    }
    {
        dim3 grid(3 * C_ / 32, C_ / 32), blk(32, 8);
        cvt_transpose_kernel<<<grid, blk>>>(w_qkv, wq, C_, 3 * C_);
    }
    {
        dim3 grid(C_ / 32, C_ / 32), blk(32, 8);
        cvt_transpose_kernel<<<grid, blk>>>(w_out, wo, C_, C_);
    }

    // 1) qkv (split fp16 output)
    {
        dim3 grid(3 * C_ / BN, BT_ / BM);
        gemm_f16x2<true><<<grid, 256, GSMEM_TOTAL>>>(xh, xl, wq,
                                                     nullptr, qkvh, qkvl, BT_, 3 * C_, C_);
    }
    // 1b) E8 projections
    {
        proj_kernel<<<(BT_ * H_) / 256, 256>>>(qkvh, qkvl, head_scales, head_dirs, bq, kp);
    }
    // 2) attention (split fp16 output)
    {
        dim3 grid(T_ / 128, B_ * H_);
        attn_mma<<<grid, 256, ATT_SMEM>>>(qkvh, qkvl, bq, kp, ah, al);
    }
    // 3) out = att @ w_out (fp32 output)
    {
        dim3 grid(C_ / BN, BT_ / BM);
        gemm_f16x2<false><<<grid, 256, GSMEM_TOTAL>>>(ah, al, wo,
                                                      out, nullptr, nullptr, BT_, C_, C_);
    }
}

// round 14
// speedup vs baseline: 1.1954x; 1.1954x over previous
#include <cuda_runtime.h>
#include <cuda_fp16.h>
#include <math.h>
#include <stdint.h>

#define B_  2
#define T_  2048
#define C_  1024
#define H_  16
#define HD_ 64
#define SCALE_ 0.125f
#define BT_ (B_ * T_)

typedef __half hf;
typedef uint32_t u32;

// ---------------- scratch ----------------
__device__ hf g_xh[(size_t)BT_ * C_];
__device__ hf g_xl[(size_t)BT_ * C_];
__device__ hf g_qkvh[(size_t)BT_ * 3 * C_];
__device__ hf g_qkvl[(size_t)BT_ * 3 * C_];
__device__ hf g_ah[(size_t)BT_ * C_];
__device__ hf g_al[(size_t)BT_ * C_];
__device__ hf g_wq[(size_t)3 * C_ * C_];
__device__ hf g_wo[(size_t)C_ * C_];
__device__ float g_bq[(size_t)B_ * H_ * T_];
__device__ float g_kp[(size_t)B_ * H_ * T_];

// ---------------- helpers ----------------
__device__ __forceinline__ u32 smem_u32(const void* p) {
    return (u32)__cvta_generic_to_shared(p);
}
__device__ __forceinline__ void ldsm_x4(u32* r, u32 addr) {
    asm volatile("ldmatrix.sync.aligned.m8n8.x4.shared.b16 {%0,%1,%2,%3}, [%4];"
        : "=r"(r[0]), "=r"(r[1]), "=r"(r[2]), "=r"(r[3]) : "r"(addr));
}
__device__ __forceinline__ void ldsm_x2(u32* r, u32 addr) {
    asm volatile("ldmatrix.sync.aligned.m8n8.x2.shared.b16 {%0,%1}, [%2];"
        : "=r"(r[0]), "=r"(r[1]) : "r"(addr));
}
__device__ __forceinline__ void ldsm_x2t(u32* r, u32 addr) {
    asm volatile("ldmatrix.sync.aligned.m8n8.x2.trans.shared.b16 {%0,%1}, [%2];"
        : "=r"(r[0]), "=r"(r[1]) : "r"(addr));
}
__device__ __forceinline__ void mma_f16(float* c, const u32* a, const u32* b) {
    asm volatile("mma.sync.aligned.m16n8k16.row.col.f32.f16.f16.f32 "
        "{%0,%1,%2,%3}, {%4,%5,%6,%7}, {%8,%9}, {%0,%1,%2,%3};"
        : "+f"(c[0]), "+f"(c[1]), "+f"(c[2]), "+f"(c[3])
        : "r"(a[0]), "r"(a[1]), "r"(a[2]), "r"(a[3]), "r"(b[0]), "r"(b[1]));
}
__device__ __forceinline__ void split2h(float a, float b, u32& hi, u32& lo) {
    __half ha = __float2half_rn(a), hb = __float2half_rn(b);
    __half2 H = __halves2half2(ha, hb);
    __half2 L = __halves2half2(__float2half_rn(a - __half2float(ha)),
                               __float2half_rn(b - __half2float(hb)));
    hi = *(u32*)&H;
    lo = *(u32*)&L;
}
__device__ __forceinline__ void cp16(u32 dst, const void* src) {
    asm volatile("cp.async.cg.shared.global [%0], [%1], 16;" :: "r"(dst), "l"(src));
}
#define CP_COMMIT() asm volatile("cp.async.commit_group;" ::: "memory")
#define CP_WAIT(n)  asm volatile("cp.async.wait_group %0;" :: "n"(n) : "memory")

// ---------------------------------------------------------------------------
// split fp32 -> (fp16 hi, fp16 lo)
// ---------------------------------------------------------------------------
__global__ void split_kernel(const float* __restrict__ src,
                             hf* __restrict__ hi, hf* __restrict__ lo, int n4)
{
    int i = blockIdx.x * blockDim.x + threadIdx.x;
    if (i >= n4) return;
    float4 v = ((const float4*)src)[i];
    u32 h0, l0, h1, l1;
    split2h(v.x, v.y, h0, l0);
    split2h(v.z, v.w, h1, l1);
    ((u32*)hi)[2 * i]     = h0;
    ((u32*)hi)[2 * i + 1] = h1;
    ((u32*)lo)[2 * i]     = l0;
    ((u32*)lo)[2 * i + 1] = l1;
}

// convert + transpose: src fp32 [K][N] -> fp16 [N][K]
__global__ void cvt_transpose_kernel(const float* __restrict__ src,
                                     hf* __restrict__ dst, int K, int N)
{
    __shared__ float tile[32][33];
    const int n0 = blockIdx.x * 32, k0 = blockIdx.y * 32;
    const int tx = threadIdx.x, ty = threadIdx.y;
    for (int r = ty; r < 32; r += 8)
        tile[r][tx] = src[(size_t)(k0 + r) * N + n0 + tx];
    __syncthreads();
    for (int r = ty; r < 32; r += 8)
        dst[(size_t)(n0 + r) * K + k0 + tx] = __float2half_rn(tile[tx][r]);
}

// ---------------------------------------------------------------------------
// E8 projections (full precision from hi+lo)
// ---------------------------------------------------------------------------
__global__ void proj_kernel(const hf* __restrict__ qkvh, const hf* __restrict__ qkvl,
                            const float* __restrict__ head_scales,
                            const float* __restrict__ head_dirs,
                            float* __restrict__ bq, float* __restrict__ kp)
{
    const int i = blockIdx.x * blockDim.x + threadIdx.x;
    if (i >= BT_ * H_) return;
    const int bt = i >> 4;
    const int h  = i & 15;
    const size_t base = (size_t)bt * (3 * C_) + h * HD_;
    float qp = 0.f, kv = 0.f;
    #pragma unroll
    for (int d = 0; d < 8; d++) {
        const float dir = head_dirs[h * 8 + d];
        qp += (__half2float(qkvh[base + d]) + __half2float(qkvl[base + d])) * dir;
        kv += __half2float(qkvh[base + C_ + d]) * dir;
    }
    const int b = bt >> 11;
    const int t = bt & (T_ - 1);
    const size_t idx = (size_t)(b * H_ + h) * T_ + t;
    bq[idx] = head_scales[h] * qp;
    kp[idx] = kv;
}

// ---------------------------------------------------------------------------
// fp16x2 GEMM (R11/R12 best config): hi+lo fp32 acc. Block 128x128x32,
// 8 warps (2m x 4n) 64x32 warp tiles. cp.async 3-stage. 2 CTAs/SM.
// ---------------------------------------------------------------------------
#define BM 128
#define BN 128
#define BK 32
#define SPITCH 40
#define PLANE_BYTES (BM * SPITCH * 2)
#define GSTAGE (3 * PLANE_BYTES)
#define NSTAGES 3
#define GSMEM_TOTAL (NSTAGES * GSTAGE)

template<bool SPLIT>
__global__ __launch_bounds__(256, 2) void gemm_f16x2(
    const hf* __restrict__ Ah, const hf* __restrict__ Al,
    const hf* __restrict__ Bs,
    float* __restrict__ Cm, hf* __restrict__ Ch, hf* __restrict__ Cl,
    int M, int N, int K)
{
    extern __shared__ char gsm[];
    const u32 sb = smem_u32(gsm);

    const int tid  = threadIdx.x;
    const int lane = tid & 31, wid = tid >> 5;
    const int wm = (wid & 1) * 64;
    const int wn = (wid >> 1) * 32;
    const int row0 = blockIdx.y * BM;
    const int col0 = blockIdx.x * BN;

    const int gr = tid >> 1;
    const int gc = (tid & 1) * 16;
    const hf* pAh = Ah + (size_t)(row0 + gr) * K + gc;
    const hf* pAl = Al + (size_t)(row0 + gr) * K + gc;
    const hf* pB  = Bs + (size_t)(col0 + gr) * K + gc;
    const u32 dstoff = (u32)(gr * (SPITCH * 2) + gc * 2);

    float acc[4][4][4];
    #pragma unroll
    for (int i = 0; i < 4; i++)
        #pragma unroll
        for (int j = 0; j < 4; j++)
            #pragma unroll
            for (int k = 0; k < 4; k++) acc[i][j][k] = 0.f;

    const int sub = lane >> 3, li = lane & 7;
    const int arow = (sub & 1) * 8 + li;
    const int acol = (sub >> 1) * 8;
    const int brow = lane & 7;
    const int bcol = ((lane >> 3) & 1) * 8;

    const int nk = K / BK;

    #define LOAD_STAGE(ic, s) do { \
        const u32 _b = sb + (s) * GSTAGE + dstoff; \
        const size_t _ko = (size_t)(ic) * BK; \
        cp16(_b,                        pAh + _ko); \
        cp16(_b + 16,                   pAh + _ko + 8); \
        cp16(_b + PLANE_BYTES,          pAl + _ko); \
        cp16(_b + PLANE_BYTES + 16,     pAl + _ko + 8); \
        cp16(_b + 2 * PLANE_BYTES,      pB + _ko); \
        cp16(_b + 2 * PLANE_BYTES + 16, pB + _ko + 8); \
    } while (0)

    LOAD_STAGE(0, 0); CP_COMMIT();
    LOAD_STAGE(1, 1); CP_COMMIT();

    int st = 0;
    for (int ic = 0; ic < nk; ic++) {
        if (ic + 1 < nk) { CP_WAIT(1); } else { CP_WAIT(0); }
        __syncthreads();

        const u32 bAh = sb + st * GSTAGE;
        const u32 bAl = bAh + PLANE_BYTES;
        const u32 bB  = bAh + 2 * PLANE_BYTES;

        if (ic + 2 < nk) {
            int ws = st + 2; if (ws >= NSTAGES) ws -= NSTAGES;
            LOAD_STAGE(ic + 2, ws); CP_COMMIT();
        }

        #pragma unroll
        for (int ks = 0; ks < BK; ks += 16) {
            u32 fB[4][2];
            #pragma unroll
            for (int nf = 0; nf < 4; nf++) {
                u32 off = (u32)(((wn + nf * 8 + brow) * SPITCH + ks + bcol) * 2);
                ldsm_x2(fB[nf], bB + off);
            }
            u32 fA[4][4];
            #pragma unroll
            for (int mf = 0; mf < 4; mf++) {
                u32 off = (u32)(((wm + mf * 16 + arow) * SPITCH + ks + acol) * 2);
                ldsm_x4(fA[mf], bAh + off);
            }
            #pragma unroll
            for (int mf = 0; mf < 4; mf++)
                #pragma unroll
                for (int nf = 0; nf < 4; nf++)
                    mma_f16(acc[mf][nf], fA[mf], fB[nf]);
            #pragma unroll
            for (int mf = 0; mf < 4; mf++) {
                u32 off = (u32)(((wm + mf * 16 + arow) * SPITCH + ks + acol) * 2);
                ldsm_x4(fA[mf], bAl + off);
            }
            #pragma unroll
            for (int mf = 0; mf < 4; mf++)
                #pragma unroll
                for (int nf = 0; nf < 4; nf++)
                    mma_f16(acc[mf][nf], fA[mf], fB[nf]);
        }
        if (++st == NSTAGES) st = 0;
    }
    #undef LOAD_STAGE

    const int g = lane >> 2, t4 = lane & 3;
    #pragma unroll
    for (int mf = 0; mf < 4; mf++) {
        #pragma unroll
        for (int nf = 0; nf < 4; nf++) {
            const float* c = acc[mf][nf];
            const size_t r  = (size_t)(row0 + wm + mf * 16 + g);
            const size_t cc = (size_t)(col0 + wn + nf * 8 + 2 * t4);
            if (!SPLIT) {
                *(float2*)&Cm[r * N + cc]       = make_float2(c[0], c[1]);
                *(float2*)&Cm[(r + 8) * N + cc] = make_float2(c[2], c[3]);
            } else {
                u32 h01, l01, h23, l23;
                split2h(c[0], c[1], h01, l01);
                split2h(c[2], c[3], h23, l23);
                *(u32*)&Ch[r * N + cc]       = h01;
                *(u32*)&Cl[r * N + cc]       = l01;
                *(u32*)&Ch[(r + 8) * N + cc] = h23;
                *(u32*)&Cl[(r + 8) * N + cc] = l23;
            }
        }
    }
}

// ---------------------------------------------------------------------------
// fp16 flash attention + E8 rank-1 bias. QK hi-only (lo term negligible
// through softmax); PV keeps P hi/lo split. cp.async 2-stage K/V + kp.
// ---------------------------------------------------------------------------
#define KPITCH 72
#define APL (64 * KPITCH * 2)

__global__ __launch_bounds__(256, 1) void attn_mma(
    const hf* __restrict__ qkvh,
    const float* __restrict__ gbq, const float* __restrict__ gkp,
    hf* __restrict__ atth, hf* __restrict__ attl)
{
    extern __shared__ hf dsm[];
    hf* sQh = dsm;                        // 128 x KPITCH (hi only)
    hf* sKV = sQh + 128 * KPITCH;         // 2 stages x 2 planes x 64 x KPITCH
    float* skp = (float*)(sKV + 4 * 64 * KPITCH);   // 2 stages x 64 floats

    const u32 kvb  = smem_u32(sKV);
    const u32 skpb = smem_u32(skp);

    const int tid  = threadIdx.x;
    const int lane = tid & 31, wid = tid >> 5;
    const int wm   = wid * 16;
    const int bh   = blockIdx.y;
    const int b    = bh >> 4;
    const int h    = bh & 15;
    const int qi   = (int)gridDim.x - 1 - (int)blockIdx.x;
    const int q0   = qi * 128;

    // Q tile (hi only): 4 int4 per thread
    #pragma unroll
    for (int i = tid; i < 128 * 8; i += 256) {
        const int row = i >> 3, seg = (i & 7) * 8;
        const size_t gb = (size_t)(b * T_ + q0 + row) * (3 * C_) + h * HD_ + seg;
        *(int4*)&sQh[row * KPITCH + seg] = *(const int4*)(qkvh + gb);
    }

    const int ktmax = 2 * qi + 2;

    #define LOAD_TILE(kt, s) do { \
        const int _k0 = (kt) * 64; \
        const u32 _sb = kvb + (s) * (2 * APL); \
        _Pragma("unroll") \
        for (int _j = 0; _j < 2; _j++) { \
            const int _i = tid + _j * 256; \
            const int _row = _i >> 3, _seg = (_i & 7) * 8; \
            const size_t _gb = (size_t)(b * T_ + _k0 + _row) * (3 * C_) + h * HD_ + _seg; \
            const u32 _d = _sb + (u32)(_row * (KPITCH * 2) + _seg * 2); \
            cp16(_d,       qkvh + _gb + C_); \
            cp16(_d + APL, qkvh + _gb + 2 * C_); \
        } \
        if (tid < 16) \
            cp16(skpb + (s) * 256 + tid * 16, gkp + (size_t)bh * T_ + _k0 + tid * 4); \
    } while (0)

    LOAD_TILE(0, 0); CP_COMMIT();
    __syncthreads();

    const int sub = lane >> 3, li = lane & 7;
    const int arow = (sub & 1) * 8 + li;
    const int acol = (sub >> 1) * 8;
    const u32 baseQh = smem_u32(sQh);
    u32 qfh[4][4];
    #pragma unroll
    for (int ks = 0; ks < 4; ks++) {
        u32 off = (u32)(((wm + arow) * KPITCH + ks * 16 + acol) * 2);
        ldsm_x4(qfh[ks], baseQh + off);
    }

    const int g = lane >> 2, t4 = lane & 3;
    const int row_g0 = q0 + wm + g;
    const int row_g1 = row_g0 + 8;
    const float bq0 = gbq[(size_t)bh * T_ + row_g0];
    const float bq1 = gbq[(size_t)bh * T_ + row_g1];

    float m0 = -INFINITY, m1 = -INFINITY, l0 = 0.f, l1 = 0.f;
    float o[8][4];
    #pragma unroll
    for (int j = 0; j < 8; j++)
        #pragma unroll
        for (int e = 0; e < 4; e++) o[j][e] = 0.f;

    const int brow = lane & 7;
    const int bcol = ((lane >> 3) & 1) * 8;
    const int vrow = lane & 15;

    for (int kt = 0; kt < ktmax; kt++) {
        const int s = kt & 1;
        const int k0 = kt * 64;

        CP_WAIT(0);
        __syncthreads();
        if (kt + 1 < ktmax) { LOAD_TILE(kt + 1, 1 - s); CP_COMMIT(); }

        const u32 bK = kvb + s * (2 * APL);
        const u32 bV = bK + APL;
        const float* kp_s = skp + s * 64;

        float s_[8][4];
        #pragma unroll
        for (int j = 0; j < 8; j++)
            #pragma unroll
            for (int e = 0; e < 4; e++) s_[j][e] = 0.f;

        // QK: hi-only
        #pragma unroll
        for (int ks = 0; ks < 4; ks++) {
            #pragma unroll
            for (int j = 0; j < 8; j++) {
                u32 kf[2];
                const u32 off = (u32)(((j * 8 + brow) * KPITCH + ks * 16 + bcol) * 2);
                ldsm_x2(kf, bK + off);
                mma_f16(s_[j], qfh[ks], kf);
            }
        }

        const bool need_mask = (kt >= 2 * qi);
        #pragma unroll
        for (int j = 0; j < 8; j++) {
            const float2 kp = *(const float2*)&kp_s[j * 8 + 2 * t4];
            s_[j][0] = s_[j][0] * SCALE_ + bq0 * kp.x;
            s_[j][1] = s_[j][1] * SCALE_ + bq0 * kp.y;
            s_[j][2] = s_[j][2] * SCALE_ + bq1 * kp.x;
            s_[j][3] = s_[j][3] * SCALE_ + bq1 * kp.y;
            if (need_mask) {
                const int key0 = k0 + j * 8 + 2 * t4;
                if (key0 > row_g0)     s_[j][0] = -INFINITY;
                if (key0 + 1 > row_g0) s_[j][1] = -INFINITY;
                if (key0 > row_g1)     s_[j][2] = -INFINITY;
                if (key0 + 1 > row_g1) s_[j][3] = -INFINITY;
            }
        }

        float mx0 = s_[0][0], mx1 = s_[0][2];
        #pragma unroll
        for (int j = 0; j < 8; j++) {
            mx0 = fmaxf(mx0, fmaxf(s_[j][0], s_[j][1]));
            mx1 = fmaxf(mx1, fmaxf(s_[j][2], s_[j][3]));
        }
        mx0 = fmaxf(mx0, __shfl_xor_sync(0xffffffffu, mx0, 1));
        mx0 = fmaxf(mx0, __shfl_xor_sync(0xffffffffu, mx0, 2));
        mx1 = fmaxf(mx1, __shfl_xor_sync(0xffffffffu, mx1, 1));
        mx1 = fmaxf(mx1, __shfl_xor_sync(0xffffffffu, mx1, 2));

        const float mn0 = fmaxf(m0, mx0), mn1 = fmaxf(m1, mx1);
        const float a0 = __expf(m0 - mn0), a1 = __expf(m1 - mn1);
        m0 = mn0; m1 = mn1;

        float rs0 = 0.f, rs1 = 0.f;
        #pragma unroll
        for (int j = 0; j < 8; j++) {
            s_[j][0] = __expf(s_[j][0] - m0);
            s_[j][1] = __expf(s_[j][1] - m0);
            s_[j][2] = __expf(s_[j][2] - m1);
            s_[j][3] = __expf(s_[j][3] - m1);
            rs0 += s_[j][0] + s_[j][1];
            rs1 += s_[j][2] + s_[j][3];
        }
        rs0 += __shfl_xor_sync(0xffffffffu, rs0, 1);
        rs0 += __shfl_xor_sync(0xffffffffu, rs0, 2);
        rs1 += __shfl_xor_sync(0xffffffffu, rs1, 1);
        rs1 += __shfl_xor_sync(0xffffffffu, rs1, 2);
        l0 = l0 * a0 + rs0;
        l1 = l1 * a1 + rs1;

        #pragma unroll
        for (int j = 0; j < 8; j++) {
            o[j][0] *= a0; o[j][1] *= a0;
            o[j][2] *= a1; o[j][3] *= a1;
        }

        // P fragments: keep hi/lo split (direct output-error path)
        u32 pah[4][4], pal[4][4];
        #pragma unroll
        for (int s2 = 0; s2 < 4; s2++) {
            split2h(s_[2 * s2][0],     s_[2 * s2][1],     pah[s2][0], pal[s2][0]);
            split2h(s_[2 * s2][2],     s_[2 * s2][3],     pah[s2][1], pal[s2][1]);
            split2h(s_[2 * s2 + 1][0], s_[2 * s2 + 1][1], pah[s2][2], pal[s2][2]);
            split2h(s_[2 * s2 + 1][2], s_[2 * s2 + 1][3], pah[s2][3], pal[s2][3]);
        }

        #pragma unroll
        for (int s2 = 0; s2 < 4; s2++) {
            #pragma unroll
            for (int j = 0; j < 8; j++) {
                u32 vf[2];
                const u32 off = (u32)(((s2 * 16 + vrow) * KPITCH + j * 8) * 2);
                ldsm_x2t(vf, bV + off);
                mma_f16(o[j], pah[s2], vf);
                mma_f16(o[j], pal[s2], vf);
            }
        }
    }
    #undef LOAD_TILE

    const float inv0 = 1.f / l0, inv1 = 1.f / l1;
    #pragma unroll
    for (int j = 0; j < 8; j++) {
        u32 h01, l01, h23, l23;
        split2h(o[j][0] * inv0, o[j][1] * inv0, h01, l01);
        split2h(o[j][2] * inv1, o[j][3] * inv1, h23, l23);
        const size_t r0o = (size_t)(b * T_ + row_g0) * C_ + h * HD_ + j * 8 + 2 * t4;
        const size_t r1o = (size_t)(b * T_ + row_g1) * C_ + h * HD_ + j * 8 + 2 * t4;
        *(u32*)&atth[r0o] = h01;
        *(u32*)&attl[r0o] = l01;
        *(u32*)&atth[r1o] = h23;
        *(u32*)&attl[r1o] = l23;
    }
}

// ---------------------------------------------------------------------------
extern "C" void kernel_launch(void* const* d_in, const int* in_sizes, int n_in,
                              void* d_out, int out_size)
{
    const float* x           = (const float*)d_in[0];
    const float* w_qkv       = (const float*)d_in[1];
    const float* w_out       = (const float*)d_in[2];
    const float* head_scales = (const float*)d_in[3];
    const float* head_dirs   = (const float*)d_in[4];
    float*       out         = (float*)d_out;

    hf *xh, *xl, *qkvh, *qkvl, *ah, *al, *wq, *wo;
    float *bq, *kp;
    cudaGetSymbolAddress((void**)&xh, g_xh);
    cudaGetSymbolAddress((void**)&xl, g_xl);
    cudaGetSymbolAddress((void**)&qkvh, g_qkvh);
    cudaGetSymbolAddress((void**)&qkvl, g_qkvl);
    cudaGetSymbolAddress((void**)&ah, g_ah);
    cudaGetSymbolAddress((void**)&al, g_al);
    cudaGetSymbolAddress((void**)&wq, g_wq);
    cudaGetSymbolAddress((void**)&wo, g_wo);
    cudaGetSymbolAddress((void**)&bq, g_bq);
    cudaGetSymbolAddress((void**)&kp, g_kp);

    const int ATT_SMEM = (128 + 64 * 4) * KPITCH * (int)sizeof(hf)
                       + 2 * 64 * (int)sizeof(float);
    cudaFuncSetAttribute(attn_mma, cudaFuncAttributeMaxDynamicSharedMemorySize, ATT_SMEM);
    cudaFuncSetAttribute(gemm_f16x2<true>,  cudaFuncAttributeMaxDynamicSharedMemorySize, GSMEM_TOTAL);
    cudaFuncSetAttribute(gemm_f16x2<false>, cudaFuncAttributeMaxDynamicSharedMemorySize, GSMEM_TOTAL);

    // splits / converts
    {
        int n4 = BT_ * C_ / 4;
        split_kernel<<<(n4 + 255) / 256, 256>>>(x, xh, xl, n4);
    }
    {
        dim3 grid(3 * C_ / 32, C_ / 32), blk(32, 8);
        cvt_transpose_kernel<<<grid, blk>>>(w_qkv, wq, C_, 3 * C_);
    }
    {
        dim3 grid(C_ / 32, C_ / 32), blk(32, 8);
        cvt_transpose_kernel<<<grid, blk>>>(w_out, wo, C_, C_);
    }

    // 1) qkv (split fp16 output)
    {
        dim3 grid(3 * C_ / BN, BT_ / BM);
        gemm_f16x2<true><<<grid, 256, GSMEM_TOTAL>>>(xh, xl, wq,
                                                     nullptr, qkvh, qkvl, BT_, 3 * C_, C_);
    }
    // 1b) E8 projections
    {
        proj_kernel<<<(BT_ * H_) / 256, 256>>>(qkvh, qkvl, head_scales, head_dirs, bq, kp);
    }
    // 2) attention (split fp16 output)
    {
        dim3 grid(T_ / 128, B_ * H_);
        attn_mma<<<grid, 256, ATT_SMEM>>>(qkvh, bq, kp, ah, al);
    }
    // 3) out = att @ w_out (fp32 output)
    {
        dim3 grid(C_ / BN, BT_ / BM);
        gemm_f16x2<false><<<grid, 256, GSMEM_TOTAL>>>(ah, al, wo,
                                                      out, nullptr, nullptr, BT_, C_, C_);
    }
}

// round 15
// speedup vs baseline: 1.3915x; 1.1640x over previous
#include <cuda_runtime.h>
#include <cuda_fp16.h>
#include <math.h>
#include <stdint.h>

#define B_  2
#define T_  2048
#define C_  1024
#define H_  16
#define HD_ 64
#define SCALE_ 0.125f
#define BT_ (B_ * T_)

typedef __half hf;
typedef uint32_t u32;

// ---------------- scratch ----------------
__device__ hf g_xh[(size_t)BT_ * C_];
__device__ hf g_xl[(size_t)BT_ * C_];
__device__ hf g_qkvh[(size_t)BT_ * 3 * C_];
__device__ hf g_qkvl[(size_t)BT_ * 3 * C_];
__device__ hf g_ah[(size_t)BT_ * C_];
__device__ hf g_al[(size_t)BT_ * C_];
__device__ hf g_wq[(size_t)3 * C_ * C_];
__device__ hf g_wo[(size_t)C_ * C_];
__device__ float g_bq[(size_t)B_ * H_ * T_];
__device__ float g_kp[(size_t)B_ * H_ * T_];

// ---------------- helpers ----------------
__device__ __forceinline__ u32 smem_u32(const void* p) {
    return (u32)__cvta_generic_to_shared(p);
}
__device__ __forceinline__ void ldsm_x4(u32* r, u32 addr) {
    asm volatile("ldmatrix.sync.aligned.m8n8.x4.shared.b16 {%0,%1,%2,%3}, [%4];"
        : "=r"(r[0]), "=r"(r[1]), "=r"(r[2]), "=r"(r[3]) : "r"(addr));
}
__device__ __forceinline__ void ldsm_x2(u32* r, u32 addr) {
    asm volatile("ldmatrix.sync.aligned.m8n8.x2.shared.b16 {%0,%1}, [%2];"
        : "=r"(r[0]), "=r"(r[1]) : "r"(addr));
}
__device__ __forceinline__ void ldsm_x2t(u32* r, u32 addr) {
    asm volatile("ldmatrix.sync.aligned.m8n8.x2.trans.shared.b16 {%0,%1}, [%2];"
        : "=r"(r[0]), "=r"(r[1]) : "r"(addr));
}
__device__ __forceinline__ void mma_f16(float* c, const u32* a, const u32* b) {
    asm volatile("mma.sync.aligned.m16n8k16.row.col.f32.f16.f16.f32 "
        "{%0,%1,%2,%3}, {%4,%5,%6,%7}, {%8,%9}, {%0,%1,%2,%3};"
        : "+f"(c[0]), "+f"(c[1]), "+f"(c[2]), "+f"(c[3])
        : "r"(a[0]), "r"(a[1]), "r"(a[2]), "r"(a[3]), "r"(b[0]), "r"(b[1]));
}
__device__ __forceinline__ void split2h(float a, float b, u32& hi, u32& lo) {
    __half ha = __float2half_rn(a), hb = __float2half_rn(b);
    __half2 H = __halves2half2(ha, hb);
    __half2 L = __halves2half2(__float2half_rn(a - __half2float(ha)),
                               __float2half_rn(b - __half2float(hb)));
    hi = *(u32*)&H;
    lo = *(u32*)&L;
}
__device__ __forceinline__ void cp16(u32 dst, const void* src) {
    asm volatile("cp.async.cg.shared.global [%0], [%1], 16;" :: "r"(dst), "l"(src));
}
#define CP_COMMIT() asm volatile("cp.async.commit_group;" ::: "memory")
#define CP_WAIT(n)  asm volatile("cp.async.wait_group %0;" :: "n"(n) : "memory")

// ---------------------------------------------------------------------------
// split fp32 -> (fp16 hi, fp16 lo)
// ---------------------------------------------------------------------------
__global__ void split_kernel(const float* __restrict__ src,
                             hf* __restrict__ hi, hf* __restrict__ lo, int n4)
{
    int i = blockIdx.x * blockDim.x + threadIdx.x;
    if (i >= n4) return;
    float4 v = ((const float4*)src)[i];
    u32 h0, l0, h1, l1;
    split2h(v.x, v.y, h0, l0);
    split2h(v.z, v.w, h1, l1);
    ((u32*)hi)[2 * i]     = h0;
    ((u32*)hi)[2 * i + 1] = h1;
    ((u32*)lo)[2 * i]     = l0;
    ((u32*)lo)[2 * i + 1] = l1;
}

// convert + transpose: src fp32 [K][N] -> fp16 [N][K]
__global__ void cvt_transpose_kernel(const float* __restrict__ src,
                                     hf* __restrict__ dst, int K, int N)
{
    __shared__ float tile[32][33];
    const int n0 = blockIdx.x * 32, k0 = blockIdx.y * 32;
    const int tx = threadIdx.x, ty = threadIdx.y;
    for (int r = ty; r < 32; r += 8)
        tile[r][tx] = src[(size_t)(k0 + r) * N + n0 + tx];
    __syncthreads();
    for (int r = ty; r < 32; r += 8)
        dst[(size_t)(n0 + r) * K + k0 + tx] = __float2half_rn(tile[tx][r]);
}

// ---------------------------------------------------------------------------
// E8 projections (full precision from hi+lo)
// ---------------------------------------------------------------------------
__global__ void proj_kernel(const hf* __restrict__ qkvh, const hf* __restrict__ qkvl,
                            const float* __restrict__ head_scales,
                            const float* __restrict__ head_dirs,
                            float* __restrict__ bq, float* __restrict__ kp)
{
    const int i = blockIdx.x * blockDim.x + threadIdx.x;
    if (i >= BT_ * H_) return;
    const int bt = i >> 4;
    const int h  = i & 15;
    const size_t base = (size_t)bt * (3 * C_) + h * HD_;
    float qp = 0.f, kv = 0.f;
    #pragma unroll
    for (int d = 0; d < 8; d++) {
        const float dir = head_dirs[h * 8 + d];
        qp += (__half2float(qkvh[base + d]) + __half2float(qkvl[base + d])) * dir;
        kv += __half2float(qkvh[base + C_ + d]) * dir;
    }
    const int b = bt >> 11;
    const int t = bt & (T_ - 1);
    const size_t idx = (size_t)(b * H_ + h) * T_ + t;
    bq[idx] = head_scales[h] * qp;
    kp[idx] = kv;
}

// ---------------------------------------------------------------------------
// fp16 GEMM, optional A-lo plane. Block 128x128x32, 8 warps (2m x 4n),
// 64x32 warp tiles. cp.async 3-stage. 2 CTAs/SM.
// ---------------------------------------------------------------------------
#define BM 128
#define BN 128
#define BK 32
#define SPITCH 40
#define PLANE_BYTES (BM * SPITCH * 2)
#define GSTAGE (3 * PLANE_BYTES)
#define NSTAGES 3
#define GSMEM_TOTAL (NSTAGES * GSTAGE)

template<bool SPLIT, bool ALO>
__global__ __launch_bounds__(256, 2) void gemm_f16x2(
    const hf* __restrict__ Ah, const hf* __restrict__ Al,
    const hf* __restrict__ Bs,
    float* __restrict__ Cm, hf* __restrict__ Ch, hf* __restrict__ Cl,
    int M, int N, int K)
{
    extern __shared__ char gsm[];
    const u32 sb = smem_u32(gsm);

    const int tid  = threadIdx.x;
    const int lane = tid & 31, wid = tid >> 5;
    const int wm = (wid & 1) * 64;
    const int wn = (wid >> 1) * 32;
    const int row0 = blockIdx.y * BM;
    const int col0 = blockIdx.x * BN;

    const int gr = tid >> 1;
    const int gc = (tid & 1) * 16;
    const hf* pAh = Ah + (size_t)(row0 + gr) * K + gc;
    const hf* pAl = ALO ? (Al + (size_t)(row0 + gr) * K + gc) : nullptr;
    const hf* pB  = Bs + (size_t)(col0 + gr) * K + gc;
    const u32 dstoff = (u32)(gr * (SPITCH * 2) + gc * 2);

    float acc[4][4][4];
    #pragma unroll
    for (int i = 0; i < 4; i++)
        #pragma unroll
        for (int j = 0; j < 4; j++)
            #pragma unroll
            for (int k = 0; k < 4; k++) acc[i][j][k] = 0.f;

    const int sub = lane >> 3, li = lane & 7;
    const int arow = (sub & 1) * 8 + li;
    const int acol = (sub >> 1) * 8;
    const int brow = lane & 7;
    const int bcol = ((lane >> 3) & 1) * 8;

    const int nk = K / BK;

    #define LOAD_STAGE(ic, s) do { \
        const u32 _b = sb + (s) * GSTAGE + dstoff; \
        const size_t _ko = (size_t)(ic) * BK; \
        cp16(_b,                        pAh + _ko); \
        cp16(_b + 16,                   pAh + _ko + 8); \
        if (ALO) { \
            cp16(_b + PLANE_BYTES,      pAl + _ko); \
            cp16(_b + PLANE_BYTES + 16, pAl + _ko + 8); \
        } \
        cp16(_b + 2 * PLANE_BYTES,      pB + _ko); \
        cp16(_b + 2 * PLANE_BYTES + 16, pB + _ko + 8); \
    } while (0)

    LOAD_STAGE(0, 0); CP_COMMIT();
    LOAD_STAGE(1, 1); CP_COMMIT();

    int st = 0;
    for (int ic = 0; ic < nk; ic++) {
        if (ic + 1 < nk) { CP_WAIT(1); } else { CP_WAIT(0); }
        __syncthreads();

        const u32 bAh = sb + st * GSTAGE;
        const u32 bAl = bAh + PLANE_BYTES;
        const u32 bB  = bAh + 2 * PLANE_BYTES;

        if (ic + 2 < nk) {
            int ws = st + 2; if (ws >= NSTAGES) ws -= NSTAGES;
            LOAD_STAGE(ic + 2, ws); CP_COMMIT();
        }

        #pragma unroll
        for (int ks = 0; ks < BK; ks += 16) {
            u32 fB[4][2];
            #pragma unroll
            for (int nf = 0; nf < 4; nf++) {
                u32 off = (u32)(((wn + nf * 8 + brow) * SPITCH + ks + bcol) * 2);
                ldsm_x2(fB[nf], bB + off);
            }
            u32 fA[4][4];
            #pragma unroll
            for (int mf = 0; mf < 4; mf++) {
                u32 off = (u32)(((wm + mf * 16 + arow) * SPITCH + ks + acol) * 2);
                ldsm_x4(fA[mf], bAh + off);
            }
            #pragma unroll
            for (int mf = 0; mf < 4; mf++)
                #pragma unroll
                for (int nf = 0; nf < 4; nf++)
                    mma_f16(acc[mf][nf], fA[mf], fB[nf]);
            if (ALO) {
                #pragma unroll
                for (int mf = 0; mf < 4; mf++) {
                    u32 off = (u32)(((wm + mf * 16 + arow) * SPITCH + ks + acol) * 2);
                    ldsm_x4(fA[mf], bAl + off);
                }
                #pragma unroll
                for (int mf = 0; mf < 4; mf++)
                    #pragma unroll
                    for (int nf = 0; nf < 4; nf++)
                        mma_f16(acc[mf][nf], fA[mf], fB[nf]);
            }
        }
        if (++st == NSTAGES) st = 0;
    }
    #undef LOAD_STAGE

    const int g = lane >> 2, t4 = lane & 3;
    #pragma unroll
    for (int mf = 0; mf < 4; mf++) {
        #pragma unroll
        for (int nf = 0; nf < 4; nf++) {
            const float* c = acc[mf][nf];
            const size_t r  = (size_t)(row0 + wm + mf * 16 + g);
            const size_t cc = (size_t)(col0 + wn + nf * 8 + 2 * t4);
            if (!SPLIT) {
                *(float2*)&Cm[r * N + cc]       = make_float2(c[0], c[1]);
                *(float2*)&Cm[(r + 8) * N + cc] = make_float2(c[2], c[3]);
            } else {
                u32 h01, l01, h23, l23;
                split2h(c[0], c[1], h01, l01);
                split2h(c[2], c[3], h23, l23);
                *(u32*)&Ch[r * N + cc]       = h01;
                *(u32*)&Cl[r * N + cc]       = l01;
                *(u32*)&Ch[(r + 8) * N + cc] = h23;
                *(u32*)&Cl[(r + 8) * N + cc] = l23;
            }
        }
    }
}

// ---------------------------------------------------------------------------
// fp16 flash attention + E8 rank-1 bias. QK hi-only; PV P hi/lo split.
// cp.async 2-stage K/V + kp. (unchanged from R14)
// ---------------------------------------------------------------------------
#define KPITCH 72
#define APL (64 * KPITCH * 2)

__global__ __launch_bounds__(256, 1) void attn_mma(
    const hf* __restrict__ qkvh,
    const float* __restrict__ gbq, const float* __restrict__ gkp,
    hf* __restrict__ atth, hf* __restrict__ attl)
{
    extern __shared__ hf dsm[];
    hf* sQh = dsm;
    hf* sKV = sQh + 128 * KPITCH;
    float* skp = (float*)(sKV + 4 * 64 * KPITCH);

    const u32 kvb  = smem_u32(sKV);
    const u32 skpb = smem_u32(skp);

    const int tid  = threadIdx.x;
    const int lane = tid & 31, wid = tid >> 5;
    const int wm   = wid * 16;
    const int bh   = blockIdx.y;
    const int b    = bh >> 4;
    const int h    = bh & 15;
    const int qi   = (int)gridDim.x - 1 - (int)blockIdx.x;
    const int q0   = qi * 128;

    #pragma unroll
    for (int i = tid; i < 128 * 8; i += 256) {
        const int row = i >> 3, seg = (i & 7) * 8;
        const size_t gb = (size_t)(b * T_ + q0 + row) * (3 * C_) + h * HD_ + seg;
        *(int4*)&sQh[row * KPITCH + seg] = *(const int4*)(qkvh + gb);
    }

    const int ktmax = 2 * qi + 2;

    #define LOAD_TILE(kt, s) do { \
        const int _k0 = (kt) * 64; \
        const u32 _sb = kvb + (s) * (2 * APL); \
        _Pragma("unroll") \
        for (int _j = 0; _j < 2; _j++) { \
            const int _i = tid + _j * 256; \
            const int _row = _i >> 3, _seg = (_i & 7) * 8; \
            const size_t _gb = (size_t)(b * T_ + _k0 + _row) * (3 * C_) + h * HD_ + _seg; \
            const u32 _d = _sb + (u32)(_row * (KPITCH * 2) + _seg * 2); \
            cp16(_d,       qkvh + _gb + C_); \
            cp16(_d + APL, qkvh + _gb + 2 * C_); \
        } \
        if (tid < 16) \
            cp16(skpb + (s) * 256 + tid * 16, gkp + (size_t)bh * T_ + _k0 + tid * 4); \
    } while (0)

    LOAD_TILE(0, 0); CP_COMMIT();
    __syncthreads();

    const int sub = lane >> 3, li = lane & 7;
    const int arow = (sub & 1) * 8 + li;
    const int acol = (sub >> 1) * 8;
    const u32 baseQh = smem_u32(sQh);
    u32 qfh[4][4];
    #pragma unroll
    for (int ks = 0; ks < 4; ks++) {
        u32 off = (u32)(((wm + arow) * KPITCH + ks * 16 + acol) * 2);
        ldsm_x4(qfh[ks], baseQh + off);
    }

    const int g = lane >> 2, t4 = lane & 3;
    const int row_g0 = q0 + wm + g;
    const int row_g1 = row_g0 + 8;
    const float bq0 = gbq[(size_t)bh * T_ + row_g0];
    const float bq1 = gbq[(size_t)bh * T_ + row_g1];

    float m0 = -INFINITY, m1 = -INFINITY, l0 = 0.f, l1 = 0.f;
    float o[8][4];
    #pragma unroll
    for (int j = 0; j < 8; j++)
        #pragma unroll
        for (int e = 0; e < 4; e++) o[j][e] = 0.f;

    const int brow = lane & 7;
    const int bcol = ((lane >> 3) & 1) * 8;
    const int vrow = lane & 15;

    for (int kt = 0; kt < ktmax; kt++) {
        const int s = kt & 1;
        const int k0 = kt * 64;

        CP_WAIT(0);
        __syncthreads();
        if (kt + 1 < ktmax) { LOAD_TILE(kt + 1, 1 - s); CP_COMMIT(); }

        const u32 bK = kvb + s * (2 * APL);
        const u32 bV = bK + APL;
        const float* kp_s = skp + s * 64;

        float s_[8][4];
        #pragma unroll
        for (int j = 0; j < 8; j++)
            #pragma unroll
            for (int e = 0; e < 4; e++) s_[j][e] = 0.f;

        #pragma unroll
        for (int ks = 0; ks < 4; ks++) {
            #pragma unroll
            for (int j = 0; j < 8; j++) {
                u32 kf[2];
                const u32 off = (u32)(((j * 8 + brow) * KPITCH + ks * 16 + bcol) * 2);
                ldsm_x2(kf, bK + off);
                mma_f16(s_[j], qfh[ks], kf);
            }
        }

        const bool need_mask = (kt >= 2 * qi);
        #pragma unroll
        for (int j = 0; j < 8; j++) {
            const float2 kp = *(const float2*)&kp_s[j * 8 + 2 * t4];
            s_[j][0] = s_[j][0] * SCALE_ + bq0 * kp.x;
            s_[j][1] = s_[j][1] * SCALE_ + bq0 * kp.y;
            s_[j][2] = s_[j][2] * SCALE_ + bq1 * kp.x;
            s_[j][3] = s_[j][3] * SCALE_ + bq1 * kp.y;
            if (need_mask) {
                const int key0 = k0 + j * 8 + 2 * t4;
                if (key0 > row_g0)     s_[j][0] = -INFINITY;
                if (key0 + 1 > row_g0) s_[j][1] = -INFINITY;
                if (key0 > row_g1)     s_[j][2] = -INFINITY;
                if (key0 + 1 > row_g1) s_[j][3] = -INFINITY;
            }
        }

        float mx0 = s_[0][0], mx1 = s_[0][2];
        #pragma unroll
        for (int j = 0; j < 8; j++) {
            mx0 = fmaxf(mx0, fmaxf(s_[j][0], s_[j][1]));
            mx1 = fmaxf(mx1, fmaxf(s_[j][2], s_[j][3]));
        }
        mx0 = fmaxf(mx0, __shfl_xor_sync(0xffffffffu, mx0, 1));
        mx0 = fmaxf(mx0, __shfl_xor_sync(0xffffffffu, mx0, 2));
        mx1 = fmaxf(mx1, __shfl_xor_sync(0xffffffffu, mx1, 1));
        mx1 = fmaxf(mx1, __shfl_xor_sync(0xffffffffu, mx1, 2));

        const float mn0 = fmaxf(m0, mx0), mn1 = fmaxf(m1, mx1);
        const float a0 = __expf(m0 - mn0), a1 = __expf(m1 - mn1);
        m0 = mn0; m1 = mn1;

        float rs0 = 0.f, rs1 = 0.f;
        #pragma unroll
        for (int j = 0; j < 8; j++) {
            s_[j][0] = __expf(s_[j][0] - m0);
            s_[j][1] = __expf(s_[j][1] - m0);
            s_[j][2] = __expf(s_[j][2] - m1);
            s_[j][3] = __expf(s_[j][3] - m1);
            rs0 += s_[j][0] + s_[j][1];
            rs1 += s_[j][2] + s_[j][3];
        }
        rs0 += __shfl_xor_sync(0xffffffffu, rs0, 1);
        rs0 += __shfl_xor_sync(0xffffffffu, rs0, 2);
        rs1 += __shfl_xor_sync(0xffffffffu, rs1, 1);
        rs1 += __shfl_xor_sync(0xffffffffu, rs1, 2);
        l0 = l0 * a0 + rs0;
        l1 = l1 * a1 + rs1;

        #pragma unroll
        for (int j = 0; j < 8; j++) {
            o[j][0] *= a0; o[j][1] *= a0;
            o[j][2] *= a1; o[j][3] *= a1;
        }

        u32 pah[4][4], pal[4][4];
        #pragma unroll
        for (int s2 = 0; s2 < 4; s2++) {
            split2h(s_[2 * s2][0],     s_[2 * s2][1],     pah[s2][0], pal[s2][0]);
            split2h(s_[2 * s2][2],     s_[2 * s2][3],     pah[s2][1], pal[s2][1]);
            split2h(s_[2 * s2 + 1][0], s_[2 * s2 + 1][1], pah[s2][2], pal[s2][2]);
            split2h(s_[2 * s2 + 1][2], s_[2 * s2 + 1][3], pah[s2][3], pal[s2][3]);
        }

        #pragma unroll
        for (int s2 = 0; s2 < 4; s2++) {
            #pragma unroll
            for (int j = 0; j < 8; j++) {
                u32 vf[2];
                const u32 off = (u32)(((s2 * 16 + vrow) * KPITCH + j * 8) * 2);
                ldsm_x2t(vf, bV + off);
                mma_f16(o[j], pah[s2], vf);
                mma_f16(o[j], pal[s2], vf);
            }
        }
    }
    #undef LOAD_TILE

    const float inv0 = 1.f / l0, inv1 = 1.f / l1;
    #pragma unroll
    for (int j = 0; j < 8; j++) {
        u32 h01, l01, h23, l23;
        split2h(o[j][0] * inv0, o[j][1] * inv0, h01, l01);
        split2h(o[j][2] * inv1, o[j][3] * inv1, h23, l23);
        const size_t r0o = (size_t)(b * T_ + row_g0) * C_ + h * HD_ + j * 8 + 2 * t4;
        const size_t r1o = (size_t)(b * T_ + row_g1) * C_ + h * HD_ + j * 8 + 2 * t4;
        *(u32*)&atth[r0o] = h01;
        *(u32*)&attl[r0o] = l01;
        *(u32*)&atth[r1o] = h23;
        *(u32*)&attl[r1o] = l23;
    }
}

// ---------------------------------------------------------------------------
extern "C" void kernel_launch(void* const* d_in, const int* in_sizes, int n_in,
                              void* d_out, int out_size)
{
    const float* x           = (const float*)d_in[0];
    const float* w_qkv       = (const float*)d_in[1];
    const float* w_out       = (const float*)d_in[2];
    const float* head_scales = (const float*)d_in[3];
    const float* head_dirs   = (const float*)d_in[4];
    float*       out         = (float*)d_out;

    hf *xh, *xl, *qkvh, *qkvl, *ah, *al, *wq, *wo;
    float *bq, *kp;
    cudaGetSymbolAddress((void**)&xh, g_xh);
    cudaGetSymbolAddress((void**)&xl, g_xl);
    cudaGetSymbolAddress((void**)&qkvh, g_qkvh);
    cudaGetSymbolAddress((void**)&qkvl, g_qkvl);
    cudaGetSymbolAddress((void**)&ah, g_ah);
    cudaGetSymbolAddress((void**)&al, g_al);
    cudaGetSymbolAddress((void**)&wq, g_wq);
    cudaGetSymbolAddress((void**)&wo, g_wo);
    cudaGetSymbolAddress((void**)&bq, g_bq);
    cudaGetSymbolAddress((void**)&kp, g_kp);

    const int ATT_SMEM = (128 + 64 * 4) * KPITCH * (int)sizeof(hf)
                       + 2 * 64 * (int)sizeof(float);
    cudaFuncSetAttribute(attn_mma, cudaFuncAttributeMaxDynamicSharedMemorySize, ATT_SMEM);
    cudaFuncSetAttribute((const void*)gemm_f16x2<true, false>,
                         cudaFuncAttributeMaxDynamicSharedMemorySize, GSMEM_TOTAL);
    cudaFuncSetAttribute((const void*)gemm_f16x2<false, true>,
                         cudaFuncAttributeMaxDynamicSharedMemorySize, GSMEM_TOTAL);

    // splits / converts
    {
        int n4 = BT_ * C_ / 4;
        split_kernel<<<(n4 + 255) / 256, 256>>>(x, xh, xl, n4);
    }
    {
        dim3 grid(3 * C_ / 32, C_ / 32), blk(32, 8);
        cvt_transpose_kernel<<<grid, blk>>>(w_qkv, wq, C_, 3 * C_);
    }
    {
        dim3 grid(C_ / 32, C_ / 32), blk(32, 8);
        cvt_transpose_kernel<<<grid, blk>>>(w_out, wo, C_, C_);
    }

    // 1) qkv = x_hi @ w_hi (hi-only A; split fp16 output for proj precision)
    {
        dim3 grid(3 * C_ / BN, BT_ / BM);
        gemm_f16x2<true, false><<<grid, 256, GSMEM_TOTAL>>>(
            xh, nullptr, wq, nullptr, qkvh, qkvl, BT_, 3 * C_, C_);
    }
    // 1b) E8 projections
    {
        proj_kernel<<<(BT_ * H_) / 256, 256>>>(qkvh, qkvl, head_scales, head_dirs, bq, kp);
    }
    // 2) attention (split fp16 output)
    {
        dim3 grid(T_ / 128, B_ * H_);
        attn_mma<<<grid, 256, ATT_SMEM>>>(qkvh, bq, kp, ah, al);
    }
    // 3) out = att @ w_out (A hi+lo; fp32 output)
    {
        dim3 grid(C_ / BN, BT_ / BM);
        gemm_f16x2<false, true><<<grid, 256, GSMEM_TOTAL>>>(
            ah, al, wo, out, nullptr, nullptr, BT_, C_, C_);
    }
}

// round 16
// speedup vs baseline: 1.4942x; 1.0739x over previous
#include <cuda_runtime.h>
#include <cuda_fp16.h>
#include <math.h>
#include <stdint.h>

#define B_  2
#define T_  2048
#define C_  1024
#define H_  16
#define HD_ 64
#define SCALE_ 0.125f
#define BT_ (B_ * T_)

typedef __half hf;
typedef uint32_t u32;

// ---------------- scratch ----------------
__device__ hf g_xh[(size_t)BT_ * C_];
__device__ hf g_qkvh[(size_t)BT_ * 3 * C_];
__device__ hf g_qkvl[(size_t)BT_ * 3 * C_];
__device__ hf g_ah[(size_t)BT_ * C_];
__device__ hf g_wq[(size_t)3 * C_ * C_];
__device__ hf g_wo[(size_t)C_ * C_];
__device__ float g_bq[(size_t)B_ * H_ * T_];
__device__ float g_kp[(size_t)B_ * H_ * T_];

// ---------------- helpers ----------------
__device__ __forceinline__ u32 smem_u32(const void* p) {
    return (u32)__cvta_generic_to_shared(p);
}
__device__ __forceinline__ void ldsm_x4(u32* r, u32 addr) {
    asm volatile("ldmatrix.sync.aligned.m8n8.x4.shared.b16 {%0,%1,%2,%3}, [%4];"
        : "=r"(r[0]), "=r"(r[1]), "=r"(r[2]), "=r"(r[3]) : "r"(addr));
}
__device__ __forceinline__ void ldsm_x2(u32* r, u32 addr) {
    asm volatile("ldmatrix.sync.aligned.m8n8.x2.shared.b16 {%0,%1}, [%2];"
        : "=r"(r[0]), "=r"(r[1]) : "r"(addr));
}
__device__ __forceinline__ void ldsm_x2t(u32* r, u32 addr) {
    asm volatile("ldmatrix.sync.aligned.m8n8.x2.trans.shared.b16 {%0,%1}, [%2];"
        : "=r"(r[0]), "=r"(r[1]) : "r"(addr));
}
__device__ __forceinline__ void mma_f16(float* c, const u32* a, const u32* b) {
    asm volatile("mma.sync.aligned.m16n8k16.row.col.f32.f16.f16.f32 "
        "{%0,%1,%2,%3}, {%4,%5,%6,%7}, {%8,%9}, {%0,%1,%2,%3};"
        : "+f"(c[0]), "+f"(c[1]), "+f"(c[2]), "+f"(c[3])
        : "r"(a[0]), "r"(a[1]), "r"(a[2]), "r"(a[3]), "r"(b[0]), "r"(b[1]));
}
__device__ __forceinline__ void split2h(float a, float b, u32& hi, u32& lo) {
    __half ha = __float2half_rn(a), hb = __float2half_rn(b);
    __half2 H = __halves2half2(ha, hb);
    __half2 L = __halves2half2(__float2half_rn(a - __half2float(ha)),
                               __float2half_rn(b - __half2float(hb)));
    hi = *(u32*)&H;
    lo = *(u32*)&L;
}
__device__ __forceinline__ u32 pack2h(float a, float b) {
    __half2 H = __halves2half2(__float2half_rn(a), __float2half_rn(b));
    return *(u32*)&H;
}
__device__ __forceinline__ void cp16(u32 dst, const void* src) {
    asm volatile("cp.async.cg.shared.global [%0], [%1], 16;" :: "r"(dst), "l"(src));
}
#define CP_COMMIT() asm volatile("cp.async.commit_group;" ::: "memory")
#define CP_WAIT(n)  asm volatile("cp.async.wait_group %0;" :: "n"(n) : "memory")

// ---------------------------------------------------------------------------
// convert fp32 -> fp16 (hi only; lo plane no longer consumed anywhere)
// ---------------------------------------------------------------------------
__global__ void cvt_kernel(const float* __restrict__ src, hf* __restrict__ dst, int n4)
{
    int i = blockIdx.x * blockDim.x + threadIdx.x;
    if (i >= n4) return;
    float4 v = ((const float4*)src)[i];
    ((u32*)dst)[2 * i]     = pack2h(v.x, v.y);
    ((u32*)dst)[2 * i + 1] = pack2h(v.z, v.w);
}

// convert + transpose: src fp32 [K][N] -> fp16 [N][K]
__global__ void cvt_transpose_kernel(const float* __restrict__ src,
                                     hf* __restrict__ dst, int K, int N)
{
    __shared__ float tile[32][33];
    const int n0 = blockIdx.x * 32, k0 = blockIdx.y * 32;
    const int tx = threadIdx.x, ty = threadIdx.y;
    for (int r = ty; r < 32; r += 8)
        tile[r][tx] = src[(size_t)(k0 + r) * N + n0 + tx];
    __syncthreads();
    for (int r = ty; r < 32; r += 8)
        dst[(size_t)(n0 + r) * K + k0 + tx] = __float2half_rn(tile[tx][r]);
}

// ---------------------------------------------------------------------------
// E8 projections (full precision from qkv hi+lo planes)
// ---------------------------------------------------------------------------
__global__ void proj_kernel(const hf* __restrict__ qkvh, const hf* __restrict__ qkvl,
                            const float* __restrict__ head_scales,
                            const float* __restrict__ head_dirs,
                            float* __restrict__ bq, float* __restrict__ kp)
{
    const int i = blockIdx.x * blockDim.x + threadIdx.x;
    if (i >= BT_ * H_) return;
    const int bt = i >> 4;
    const int h  = i & 15;
    const size_t base = (size_t)bt * (3 * C_) + h * HD_;
    float qp = 0.f, kv = 0.f;
    #pragma unroll
    for (int d = 0; d < 8; d++) {
        const float dir = head_dirs[h * 8 + d];
        qp += (__half2float(qkvh[base + d]) + __half2float(qkvl[base + d])) * dir;
        kv += __half2float(qkvh[base + C_ + d]) * dir;
    }
    const int b = bt >> 11;
    const int t = bt & (T_ - 1);
    const size_t idx = (size_t)(b * H_ + h) * T_ + t;
    bq[idx] = head_scales[h] * qp;
    kp[idx] = kv;
}

// ---------------------------------------------------------------------------
// fp16 GEMM, hi-only A. Block 128x128x32, 8 warps (2m x 4n), 64x32 warp
// tiles. cp.async 3-stage. 2 CTAs/SM. SPLIT: emit hi/lo fp16 planes.
// ---------------------------------------------------------------------------
#define BM 128
#define BN 128
#define BK 32
#define SPITCH 40
#define PLANE_BYTES (BM * SPITCH * 2)
#define GSTAGE (3 * PLANE_BYTES)
#define NSTAGES 3
#define GSMEM_TOTAL (NSTAGES * GSTAGE)

template<bool SPLIT>
__global__ __launch_bounds__(256, 2) void gemm_f16(
    const hf* __restrict__ Ah, const hf* __restrict__ Bs,
    float* __restrict__ Cm, hf* __restrict__ Ch, hf* __restrict__ Cl,
    int M, int N, int K)
{
    extern __shared__ char gsm[];
    const u32 sb = smem_u32(gsm);

    const int tid  = threadIdx.x;
    const int lane = tid & 31, wid = tid >> 5;
    const int wm = (wid & 1) * 64;
    const int wn = (wid >> 1) * 32;
    const int row0 = blockIdx.y * BM;
    const int col0 = blockIdx.x * BN;

    const int gr = tid >> 1;
    const int gc = (tid & 1) * 16;
    const hf* pAh = Ah + (size_t)(row0 + gr) * K + gc;
    const hf* pB  = Bs + (size_t)(col0 + gr) * K + gc;
    const u32 dstoff = (u32)(gr * (SPITCH * 2) + gc * 2);

    float acc[4][4][4];
    #pragma unroll
    for (int i = 0; i < 4; i++)
        #pragma unroll
        for (int j = 0; j < 4; j++)
            #pragma unroll
            for (int k = 0; k < 4; k++) acc[i][j][k] = 0.f;

    const int sub = lane >> 3, li = lane & 7;
    const int arow = (sub & 1) * 8 + li;
    const int acol = (sub >> 1) * 8;
    const int brow = lane & 7;
    const int bcol = ((lane >> 3) & 1) * 8;

    const int nk = K / BK;

    #define LOAD_STAGE(ic, s) do { \
        const u32 _b = sb + (s) * GSTAGE + dstoff; \
        const size_t _ko = (size_t)(ic) * BK; \
        cp16(_b,                        pAh + _ko); \
        cp16(_b + 16,                   pAh + _ko + 8); \
        cp16(_b + 2 * PLANE_BYTES,      pB + _ko); \
        cp16(_b + 2 * PLANE_BYTES + 16, pB + _ko + 8); \
    } while (0)

    LOAD_STAGE(0, 0); CP_COMMIT();
    LOAD_STAGE(1, 1); CP_COMMIT();

    int st = 0;
    for (int ic = 0; ic < nk; ic++) {
        if (ic + 1 < nk) { CP_WAIT(1); } else { CP_WAIT(0); }
        __syncthreads();

        const u32 bAh = sb + st * GSTAGE;
        const u32 bB  = bAh + 2 * PLANE_BYTES;

        if (ic + 2 < nk) {
            int ws = st + 2; if (ws >= NSTAGES) ws -= NSTAGES;
            LOAD_STAGE(ic + 2, ws); CP_COMMIT();
        }

        #pragma unroll
        for (int ks = 0; ks < BK; ks += 16) {
            u32 fB[4][2];
            #pragma unroll
            for (int nf = 0; nf < 4; nf++) {
                u32 off = (u32)(((wn + nf * 8 + brow) * SPITCH + ks + bcol) * 2);
                ldsm_x2(fB[nf], bB + off);
            }
            u32 fA[4][4];
            #pragma unroll
            for (int mf = 0; mf < 4; mf++) {
                u32 off = (u32)(((wm + mf * 16 + arow) * SPITCH + ks + acol) * 2);
                ldsm_x4(fA[mf], bAh + off);
            }
            #pragma unroll
            for (int mf = 0; mf < 4; mf++)
                #pragma unroll
                for (int nf = 0; nf < 4; nf++)
                    mma_f16(acc[mf][nf], fA[mf], fB[nf]);
        }
        if (++st == NSTAGES) st = 0;
    }
    #undef LOAD_STAGE

    const int g = lane >> 2, t4 = lane & 3;
    #pragma unroll
    for (int mf = 0; mf < 4; mf++) {
        #pragma unroll
        for (int nf = 0; nf < 4; nf++) {
            const float* c = acc[mf][nf];
            const size_t r  = (size_t)(row0 + wm + mf * 16 + g);
            const size_t cc = (size_t)(col0 + wn + nf * 8 + 2 * t4);
            if (!SPLIT) {
                *(float2*)&Cm[r * N + cc]       = make_float2(c[0], c[1]);
                *(float2*)&Cm[(r + 8) * N + cc] = make_float2(c[2], c[3]);
            } else {
                u32 h01, l01, h23, l23;
                split2h(c[0], c[1], h01, l01);
                split2h(c[2], c[3], h23, l23);
                *(u32*)&Ch[r * N + cc]       = h01;
                *(u32*)&Cl[r * N + cc]       = l01;
                *(u32*)&Ch[(r + 8) * N + cc] = h23;
                *(u32*)&Cl[(r + 8) * N + cc] = l23;
            }
        }
    }
}

// ---------------------------------------------------------------------------
// fp16 flash attention + E8 rank-1 bias. QK hi-only; PV P hi/lo split.
// Output: hi plane only (GEMM2 is hi-only now).
// ---------------------------------------------------------------------------
#define KPITCH 72
#define APL (64 * KPITCH * 2)

__global__ __launch_bounds__(256, 1) void attn_mma(
    const hf* __restrict__ qkvh,
    const float* __restrict__ gbq, const float* __restrict__ gkp,
    hf* __restrict__ atth)
{
    extern __shared__ hf dsm[];
    hf* sQh = dsm;
    hf* sKV = sQh + 128 * KPITCH;
    float* skp = (float*)(sKV + 4 * 64 * KPITCH);

    const u32 kvb  = smem_u32(sKV);
    const u32 skpb = smem_u32(skp);

    const int tid  = threadIdx.x;
    const int lane = tid & 31, wid = tid >> 5;
    const int wm   = wid * 16;
    const int bh   = blockIdx.y;
    const int b    = bh >> 4;
    const int h    = bh & 15;
    const int qi   = (int)gridDim.x - 1 - (int)blockIdx.x;
    const int q0   = qi * 128;

    #pragma unroll
    for (int i = tid; i < 128 * 8; i += 256) {
        const int row = i >> 3, seg = (i & 7) * 8;
        const size_t gb = (size_t)(b * T_ + q0 + row) * (3 * C_) + h * HD_ + seg;
        *(int4*)&sQh[row * KPITCH + seg] = *(const int4*)(qkvh + gb);
    }

    const int ktmax = 2 * qi + 2;

    #define LOAD_TILE(kt, s) do { \
        const int _k0 = (kt) * 64; \
        const u32 _sb = kvb + (s) * (2 * APL); \
        _Pragma("unroll") \
        for (int _j = 0; _j < 2; _j++) { \
            const int _i = tid + _j * 256; \
            const int _row = _i >> 3, _seg = (_i & 7) * 8; \
            const size_t _gb = (size_t)(b * T_ + _k0 + _row) * (3 * C_) + h * HD_ + _seg; \
            const u32 _d = _sb + (u32)(_row * (KPITCH * 2) + _seg * 2); \
            cp16(_d,       qkvh + _gb + C_); \
            cp16(_d + APL, qkvh + _gb + 2 * C_); \
        } \
        if (tid < 16) \
            cp16(skpb + (s) * 256 + tid * 16, gkp + (size_t)bh * T_ + _k0 + tid * 4); \
    } while (0)

    LOAD_TILE(0, 0); CP_COMMIT();
    __syncthreads();

    const int sub = lane >> 3, li = lane & 7;
    const int arow = (sub & 1) * 8 + li;
    const int acol = (sub >> 1) * 8;
    const u32 baseQh = smem_u32(sQh);
    u32 qfh[4][4];
    #pragma unroll
    for (int ks = 0; ks < 4; ks++) {
        u32 off = (u32)(((wm + arow) * KPITCH + ks * 16 + acol) * 2);
        ldsm_x4(qfh[ks], baseQh + off);
    }

    const int g = lane >> 2, t4 = lane & 3;
    const int row_g0 = q0 + wm + g;
    const int row_g1 = row_g0 + 8;
    const float bq0 = gbq[(size_t)bh * T_ + row_g0];
    const float bq1 = gbq[(size_t)bh * T_ + row_g1];

    float m0 = -INFINITY, m1 = -INFINITY, l0 = 0.f, l1 = 0.f;
    float o[8][4];
    #pragma unroll
    for (int j = 0; j < 8; j++)
        #pragma unroll
        for (int e = 0; e < 4; e++) o[j][e] = 0.f;

    const int brow = lane & 7;
    const int bcol = ((lane >> 3) & 1) * 8;
    const int vrow = lane & 15;

    for (int kt = 0; kt < ktmax; kt++) {
        const int s = kt & 1;
        const int k0 = kt * 64;

        CP_WAIT(0);
        __syncthreads();
        if (kt + 1 < ktmax) { LOAD_TILE(kt + 1, 1 - s); CP_COMMIT(); }

        const u32 bK = kvb + s * (2 * APL);
        const u32 bV = bK + APL;
        const float* kp_s = skp + s * 64;

        float s_[8][4];
        #pragma unroll
        for (int j = 0; j < 8; j++)
            #pragma unroll
            for (int e = 0; e < 4; e++) s_[j][e] = 0.f;

        #pragma unroll
        for (int ks = 0; ks < 4; ks++) {
            #pragma unroll
            for (int j = 0; j < 8; j++) {
                u32 kf[2];
                const u32 off = (u32)(((j * 8 + brow) * KPITCH + ks * 16 + bcol) * 2);
                ldsm_x2(kf, bK + off);
                mma_f16(s_[j], qfh[ks], kf);
            }
        }

        const bool need_mask = (kt >= 2 * qi);
        #pragma unroll
        for (int j = 0; j < 8; j++) {
            const float2 kp = *(const float2*)&kp_s[j * 8 + 2 * t4];
            s_[j][0] = s_[j][0] * SCALE_ + bq0 * kp.x;
            s_[j][1] = s_[j][1] * SCALE_ + bq0 * kp.y;
            s_[j][2] = s_[j][2] * SCALE_ + bq1 * kp.x;
            s_[j][3] = s_[j][3] * SCALE_ + bq1 * kp.y;
            if (need_mask) {
                const int key0 = k0 + j * 8 + 2 * t4;
                if (key0 > row_g0)     s_[j][0] = -INFINITY;
                if (key0 + 1 > row_g0) s_[j][1] = -INFINITY;
                if (key0 > row_g1)     s_[j][2] = -INFINITY;
                if (key0 + 1 > row_g1) s_[j][3] = -INFINITY;
            }
        }

        float mx0 = s_[0][0], mx1 = s_[0][2];
        #pragma unroll
        for (int j = 0; j < 8; j++) {
            mx0 = fmaxf(mx0, fmaxf(s_[j][0], s_[j][1]));
            mx1 = fmaxf(mx1, fmaxf(s_[j][2], s_[j][3]));
        }
        mx0 = fmaxf(mx0, __shfl_xor_sync(0xffffffffu, mx0, 1));
        mx0 = fmaxf(mx0, __shfl_xor_sync(0xffffffffu, mx0, 2));
        mx1 = fmaxf(mx1, __shfl_xor_sync(0xffffffffu, mx1, 1));
        mx1 = fmaxf(mx1, __shfl_xor_sync(0xffffffffu, mx1, 2));

        const float mn0 = fmaxf(m0, mx0), mn1 = fmaxf(m1, mx1);
        const float a0 = __expf(m0 - mn0), a1 = __expf(m1 - mn1);
        m0 = mn0; m1 = mn1;

        float rs0 = 0.f, rs1 = 0.f;
        #pragma unroll
        for (int j = 0; j < 8; j++) {
            s_[j][0] = __expf(s_[j][0] - m0);
            s_[j][1] = __expf(s_[j][1] - m0);
            s_[j][2] = __expf(s_[j][2] - m1);
            s_[j][3] = __expf(s_[j][3] - m1);
            rs0 += s_[j][0] + s_[j][1];
            rs1 += s_[j][2] + s_[j][3];
        }
        rs0 += __shfl_xor_sync(0xffffffffu, rs0, 1);
        rs0 += __shfl_xor_sync(0xffffffffu, rs0, 2);
        rs1 += __shfl_xor_sync(0xffffffffu, rs1, 1);
        rs1 += __shfl_xor_sync(0xffffffffu, rs1, 2);
        l0 = l0 * a0 + rs0;
        l1 = l1 * a1 + rs1;

        #pragma unroll
        for (int j = 0; j < 8; j++) {
            o[j][0] *= a0; o[j][1] *= a0;
            o[j][2] *= a1; o[j][3] *= a1;
        }

        u32 pah[4][4], pal[4][4];
        #pragma unroll
        for (int s2 = 0; s2 < 4; s2++) {
            split2h(s_[2 * s2][0],     s_[2 * s2][1],     pah[s2][0], pal[s2][0]);
            split2h(s_[2 * s2][2],     s_[2 * s2][3],     pah[s2][1], pal[s2][1]);
            split2h(s_[2 * s2 + 1][0], s_[2 * s2 + 1][1], pah[s2][2], pal[s2][2]);
            split2h(s_[2 * s2 + 1][2], s_[2 * s2 + 1][3], pah[s2][3], pal[s2][3]);
        }

        #pragma unroll
        for (int s2 = 0; s2 < 4; s2++) {
            #pragma unroll
            for (int j = 0; j < 8; j++) {
                u32 vf[2];
                const u32 off = (u32)(((s2 * 16 + vrow) * KPITCH + j * 8) * 2);
                ldsm_x2t(vf, bV + off);
                mma_f16(o[j], pah[s2], vf);
                mma_f16(o[j], pal[s2], vf);
            }
        }
    }
    #undef LOAD_TILE

    const float inv0 = 1.f / l0, inv1 = 1.f / l1;
    #pragma unroll
    for (int j = 0; j < 8; j++) {
        const u32 h01 = pack2h(o[j][0] * inv0, o[j][1] * inv0);
        const u32 h23 = pack2h(o[j][2] * inv1, o[j][3] * inv1);
        const size_t r0o = (size_t)(b * T_ + row_g0) * C_ + h * HD_ + j * 8 + 2 * t4;
        const size_t r1o = (size_t)(b * T_ + row_g1) * C_ + h * HD_ + j * 8 + 2 * t4;
        *(u32*)&atth[r0o] = h01;
        *(u32*)&atth[r1o] = h23;
    }
}

// ---------------------------------------------------------------------------
extern "C" void kernel_launch(void* const* d_in, const int* in_sizes, int n_in,
                              void* d_out, int out_size)
{
    const float* x           = (const float*)d_in[0];
    const float* w_qkv       = (const float*)d_in[1];
    const float* w_out       = (const float*)d_in[2];
    const float* head_scales = (const float*)d_in[3];
    const float* head_dirs   = (const float*)d_in[4];
    float*       out         = (float*)d_out;

    hf *xh, *qkvh, *qkvl, *ah, *wq, *wo;
    float *bq, *kp;
    cudaGetSymbolAddress((void**)&xh, g_xh);
    cudaGetSymbolAddress((void**)&qkvh, g_qkvh);
    cudaGetSymbolAddress((void**)&qkvl, g_qkvl);
    cudaGetSymbolAddress((void**)&ah, g_ah);
    cudaGetSymbolAddress((void**)&wq, g_wq);
    cudaGetSymbolAddress((void**)&wo, g_wo);
    cudaGetSymbolAddress((void**)&bq, g_bq);
    cudaGetSymbolAddress((void**)&kp, g_kp);

    const int ATT_SMEM = (128 + 64 * 4) * KPITCH * (int)sizeof(hf)
                       + 2 * 64 * (int)sizeof(float);
    cudaFuncSetAttribute(attn_mma, cudaFuncAttributeMaxDynamicSharedMemorySize, ATT_SMEM);
    cudaFuncSetAttribute((const void*)gemm_f16<true>,
                         cudaFuncAttributeMaxDynamicSharedMemorySize, GSMEM_TOTAL);
    cudaFuncSetAttribute((const void*)gemm_f16<false>,
                         cudaFuncAttributeMaxDynamicSharedMemorySize, GSMEM_TOTAL);

    // converts
    {
        int n4 = BT_ * C_ / 4;
        cvt_kernel<<<(n4 + 255) / 256, 256>>>(x, xh, n4);
    }
    {
        dim3 grid(3 * C_ / 32, C_ / 32), blk(32, 8);
        cvt_transpose_kernel<<<grid, blk>>>(w_qkv, wq, C_, 3 * C_);
    }
    {
        dim3 grid(C_ / 32, C_ / 32), blk(32, 8);
        cvt_transpose_kernel<<<grid, blk>>>(w_out, wo, C_, C_);
    }

    // 1) qkv = x_hi @ w_hi (split hi/lo output for proj precision)
    {
        dim3 grid(3 * C_ / BN, BT_ / BM);
        gemm_f16<true><<<grid, 256, GSMEM_TOTAL>>>(
            xh, wq, nullptr, qkvh, qkvl, BT_, 3 * C_, C_);
    }
    // 1b) E8 projections
    {
        proj_kernel<<<(BT_ * H_) / 256, 256>>>(qkvh, qkvl, head_scales, head_dirs, bq, kp);
    }
    // 2) attention (hi-only output)
    {
        dim3 grid(T_ / 128, B_ * H_);
        attn_mma<<<grid, 256, ATT_SMEM>>>(qkvh, bq, kp, ah);
    }
    // 3) out = att_hi @ w_hi (fp32 output)
    {
        dim3 grid(C_ / BN, BT_ / BM);
        gemm_f16<false><<<grid, 256, GSMEM_TOTAL>>>(
            ah, wo, out, nullptr, nullptr, BT_, C_, C_);
    }
}

// round 17
// speedup vs baseline: 1.6330x; 1.0928x over previous
#include <cuda_runtime.h>
#include <cuda_fp16.h>
#include <math.h>
#include <stdint.h>

#define B_  2
#define T_  2048
#define C_  1024
#define H_  16
#define HD_ 64
#define SCALE_ 0.125f
#define BT_ (B_ * T_)

typedef __half hf;
typedef uint32_t u32;

// ---------------- scratch ----------------
__device__ hf g_xh[(size_t)BT_ * C_];
__device__ hf g_qkvh[(size_t)BT_ * 3 * C_];
__device__ hf g_qkvl[(size_t)BT_ * 3 * C_];
__device__ hf g_ah[(size_t)BT_ * C_];
__device__ hf g_wq[(size_t)3 * C_ * C_];
__device__ hf g_wo[(size_t)C_ * C_];
__device__ float g_bq[(size_t)B_ * H_ * T_];
__device__ float g_kp[(size_t)B_ * H_ * T_];

// ---------------- helpers ----------------
__device__ __forceinline__ u32 smem_u32(const void* p) {
    return (u32)__cvta_generic_to_shared(p);
}
__device__ __forceinline__ void ldsm_x4(u32* r, u32 addr) {
    asm volatile("ldmatrix.sync.aligned.m8n8.x4.shared.b16 {%0,%1,%2,%3}, [%4];"
        : "=r"(r[0]), "=r"(r[1]), "=r"(r[2]), "=r"(r[3]) : "r"(addr));
}
__device__ __forceinline__ void ldsm_x2(u32* r, u32 addr) {
    asm volatile("ldmatrix.sync.aligned.m8n8.x2.shared.b16 {%0,%1}, [%2];"
        : "=r"(r[0]), "=r"(r[1]) : "r"(addr));
}
__device__ __forceinline__ void ldsm_x2t(u32* r, u32 addr) {
    asm volatile("ldmatrix.sync.aligned.m8n8.x2.trans.shared.b16 {%0,%1}, [%2];"
        : "=r"(r[0]), "=r"(r[1]) : "r"(addr));
}
__device__ __forceinline__ void mma_f16(float* c, const u32* a, const u32* b) {
    asm volatile("mma.sync.aligned.m16n8k16.row.col.f32.f16.f16.f32 "
        "{%0,%1,%2,%3}, {%4,%5,%6,%7}, {%8,%9}, {%0,%1,%2,%3};"
        : "+f"(c[0]), "+f"(c[1]), "+f"(c[2]), "+f"(c[3])
        : "r"(a[0]), "r"(a[1]), "r"(a[2]), "r"(a[3]), "r"(b[0]), "r"(b[1]));
}
__device__ __forceinline__ void split2h(float a, float b, u32& hi, u32& lo) {
    __half ha = __float2half_rn(a), hb = __float2half_rn(b);
    __half2 H = __halves2half2(ha, hb);
    __half2 L = __halves2half2(__float2half_rn(a - __half2float(ha)),
                               __float2half_rn(b - __half2float(hb)));
    hi = *(u32*)&H;
    lo = *(u32*)&L;
}
__device__ __forceinline__ u32 pack2h(float a, float b) {
    __half2 H = __halves2half2(__float2half_rn(a), __float2half_rn(b));
    return *(u32*)&H;
}
__device__ __forceinline__ void cp16(u32 dst, const void* src) {
    asm volatile("cp.async.cg.shared.global [%0], [%1], 16;" :: "r"(dst), "l"(src));
}
#define CP_COMMIT() asm volatile("cp.async.commit_group;" ::: "memory")
#define CP_WAIT(n)  asm volatile("cp.async.wait_group %0;" :: "n"(n) : "memory")

// ---------------------------------------------------------------------------
// convert fp32 -> fp16
// ---------------------------------------------------------------------------
__global__ void cvt_kernel(const float* __restrict__ src, hf* __restrict__ dst, int n4)
{
    int i = blockIdx.x * blockDim.x + threadIdx.x;
    if (i >= n4) return;
    float4 v = ((const float4*)src)[i];
    ((u32*)dst)[2 * i]     = pack2h(v.x, v.y);
    ((u32*)dst)[2 * i + 1] = pack2h(v.z, v.w);
}

// convert + transpose: src fp32 [K][N] -> fp16 [N][K]
__global__ void cvt_transpose_kernel(const float* __restrict__ src,
                                     hf* __restrict__ dst, int K, int N)
{
    __shared__ float tile[32][33];
    const int n0 = blockIdx.x * 32, k0 = blockIdx.y * 32;
    const int tx = threadIdx.x, ty = threadIdx.y;
    for (int r = ty; r < 32; r += 8)
        tile[r][tx] = src[(size_t)(k0 + r) * N + n0 + tx];
    __syncthreads();
    for (int r = ty; r < 32; r += 8)
        dst[(size_t)(n0 + r) * K + k0 + tx] = __float2half_rn(tile[tx][r]);
}

// ---------------------------------------------------------------------------
// E8 projections (full precision from qkv hi+lo planes)
// ---------------------------------------------------------------------------
__global__ void proj_kernel(const hf* __restrict__ qkvh, const hf* __restrict__ qkvl,
                            const float* __restrict__ head_scales,
                            const float* __restrict__ head_dirs,
                            float* __restrict__ bq, float* __restrict__ kp)
{
    const int i = blockIdx.x * blockDim.x + threadIdx.x;
    if (i >= BT_ * H_) return;
    const int bt = i >> 4;
    const int h  = i & 15;
    const size_t base = (size_t)bt * (3 * C_) + h * HD_;
    float qp = 0.f, kv = 0.f;
    #pragma unroll
    for (int d = 0; d < 8; d++) {
        const float dir = head_dirs[h * 8 + d];
        qp += (__half2float(qkvh[base + d]) + __half2float(qkvl[base + d])) * dir;
        kv += __half2float(qkvh[base + C_ + d]) * dir;
    }
    const int b = bt >> 11;
    const int t = bt & (T_ - 1);
    const size_t idx = (size_t)(b * H_ + h) * T_ + t;
    bq[idx] = head_scales[h] * qp;
    kp[idx] = kv;
}

// ---------------------------------------------------------------------------
// fp16 GEMM, hi-only A. Block 128x128x32, 8 warps (2m x 4n), 64x32 warp
// tiles. cp.async 3-stage. 2 CTAs/SM. SPLIT: emit hi/lo fp16 planes.
// ---------------------------------------------------------------------------
#define BM 128
#define BN 128
#define BK 32
#define SPITCH 40
#define PLANE_BYTES (BM * SPITCH * 2)
#define GSTAGE (3 * PLANE_BYTES)
#define NSTAGES 3
#define GSMEM_TOTAL (NSTAGES * GSTAGE)

template<bool SPLIT>
__global__ __launch_bounds__(256, 2) void gemm_f16(
    const hf* __restrict__ Ah, const hf* __restrict__ Bs,
    float* __restrict__ Cm, hf* __restrict__ Ch, hf* __restrict__ Cl,
    int M, int N, int K)
{
    extern __shared__ char gsm[];
    const u32 sb = smem_u32(gsm);

    const int tid  = threadIdx.x;
    const int lane = tid & 31, wid = tid >> 5;
    const int wm = (wid & 1) * 64;
    const int wn = (wid >> 1) * 32;
    const int row0 = blockIdx.y * BM;
    const int col0 = blockIdx.x * BN;

    const int gr = tid >> 1;
    const int gc = (tid & 1) * 16;
    const hf* pAh = Ah + (size_t)(row0 + gr) * K + gc;
    const hf* pB  = Bs + (size_t)(col0 + gr) * K + gc;
    const u32 dstoff = (u32)(gr * (SPITCH * 2) + gc * 2);

    float acc[4][4][4];
    #pragma unroll
    for (int i = 0; i < 4; i++)
        #pragma unroll
        for (int j = 0; j < 4; j++)
            #pragma unroll
            for (int k = 0; k < 4; k++) acc[i][j][k] = 0.f;

    const int sub = lane >> 3, li = lane & 7;
    const int arow = (sub & 1) * 8 + li;
    const int acol = (sub >> 1) * 8;
    const int brow = lane & 7;
    const int bcol = ((lane >> 3) & 1) * 8;

    const int nk = K / BK;

    #define LOAD_STAGE(ic, s) do { \
        const u32 _b = sb + (s) * GSTAGE + dstoff; \
        const size_t _ko = (size_t)(ic) * BK; \
        cp16(_b,                        pAh + _ko); \
        cp16(_b + 16,                   pAh + _ko + 8); \
        cp16(_b + 2 * PLANE_BYTES,      pB + _ko); \
        cp16(_b + 2 * PLANE_BYTES + 16, pB + _ko + 8); \
    } while (0)

    LOAD_STAGE(0, 0); CP_COMMIT();
    LOAD_STAGE(1, 1); CP_COMMIT();

    int st = 0;
    for (int ic = 0; ic < nk; ic++) {
        if (ic + 1 < nk) { CP_WAIT(1); } else { CP_WAIT(0); }
        __syncthreads();

        const u32 bAh = sb + st * GSTAGE;
        const u32 bB  = bAh + 2 * PLANE_BYTES;

        if (ic + 2 < nk) {
            int ws = st + 2; if (ws >= NSTAGES) ws -= NSTAGES;
            LOAD_STAGE(ic + 2, ws); CP_COMMIT();
        }

        #pragma unroll
        for (int ks = 0; ks < BK; ks += 16) {
            u32 fB[4][2];
            #pragma unroll
            for (int nf = 0; nf < 4; nf++) {
                u32 off = (u32)(((wn + nf * 8 + brow) * SPITCH + ks + bcol) * 2);
                ldsm_x2(fB[nf], bB + off);
            }
            u32 fA[4][4];
            #pragma unroll
            for (int mf = 0; mf < 4; mf++) {
                u32 off = (u32)(((wm + mf * 16 + arow) * SPITCH + ks + acol) * 2);
                ldsm_x4(fA[mf], bAh + off);
            }
            #pragma unroll
            for (int mf = 0; mf < 4; mf++)
                #pragma unroll
                for (int nf = 0; nf < 4; nf++)
                    mma_f16(acc[mf][nf], fA[mf], fB[nf]);
        }
        if (++st == NSTAGES) st = 0;
    }
    #undef LOAD_STAGE

    const int g = lane >> 2, t4 = lane & 3;
    #pragma unroll
    for (int mf = 0; mf < 4; mf++) {
        #pragma unroll
        for (int nf = 0; nf < 4; nf++) {
            const float* c = acc[mf][nf];
            const size_t r  = (size_t)(row0 + wm + mf * 16 + g);
            const size_t cc = (size_t)(col0 + wn + nf * 8 + 2 * t4);
            if (!SPLIT) {
                *(float2*)&Cm[r * N + cc]       = make_float2(c[0], c[1]);
                *(float2*)&Cm[(r + 8) * N + cc] = make_float2(c[2], c[3]);
            } else {
                u32 h01, l01, h23, l23;
                split2h(c[0], c[1], h01, l01);
                split2h(c[2], c[3], h23, l23);
                *(u32*)&Ch[r * N + cc]       = h01;
                *(u32*)&Cl[r * N + cc]       = l01;
                *(u32*)&Ch[(r + 8) * N + cc] = h23;
                *(u32*)&Cl[(r + 8) * N + cc] = l23;
            }
        }
    }
}

// ---------------------------------------------------------------------------
// fp16 flash attention + E8 rank-1 bias. QK hi-only; PV hi-only (P single
// fp16 rounding). Output: hi plane only.
// ---------------------------------------------------------------------------
#define KPITCH 72
#define APL (64 * KPITCH * 2)

__global__ __launch_bounds__(256, 1) void attn_mma(
    const hf* __restrict__ qkvh,
    const float* __restrict__ gbq, const float* __restrict__ gkp,
    hf* __restrict__ atth)
{
    extern __shared__ hf dsm[];
    hf* sQh = dsm;
    hf* sKV = sQh + 128 * KPITCH;
    float* skp = (float*)(sKV + 4 * 64 * KPITCH);

    const u32 kvb  = smem_u32(sKV);
    const u32 skpb = smem_u32(skp);

    const int tid  = threadIdx.x;
    const int lane = tid & 31, wid = tid >> 5;
    const int wm   = wid * 16;
    const int bh   = blockIdx.y;
    const int b    = bh >> 4;
    const int h    = bh & 15;
    const int qi   = (int)gridDim.x - 1 - (int)blockIdx.x;
    const int q0   = qi * 128;

    #pragma unroll
    for (int i = tid; i < 128 * 8; i += 256) {
        const int row = i >> 3, seg = (i & 7) * 8;
        const size_t gb = (size_t)(b * T_ + q0 + row) * (3 * C_) + h * HD_ + seg;
        *(int4*)&sQh[row * KPITCH + seg] = *(const int4*)(qkvh + gb);
    }

    const int ktmax = 2 * qi + 2;

    #define LOAD_TILE(kt, s) do { \
        const int _k0 = (kt) * 64; \
        const u32 _sb = kvb + (s) * (2 * APL); \
        _Pragma("unroll") \
        for (int _j = 0; _j < 2; _j++) { \
            const int _i = tid + _j * 256; \
            const int _row = _i >> 3, _seg = (_i & 7) * 8; \
            const size_t _gb = (size_t)(b * T_ + _k0 + _row) * (3 * C_) + h * HD_ + _seg; \
            const u32 _d = _sb + (u32)(_row * (KPITCH * 2) + _seg * 2); \
            cp16(_d,       qkvh + _gb + C_); \
            cp16(_d + APL, qkvh + _gb + 2 * C_); \
        } \
        if (tid < 16) \
            cp16(skpb + (s) * 256 + tid * 16, gkp + (size_t)bh * T_ + _k0 + tid * 4); \
    } while (0)

    LOAD_TILE(0, 0); CP_COMMIT();
    __syncthreads();

    const int sub = lane >> 3, li = lane & 7;
    const int arow = (sub & 1) * 8 + li;
    const int acol = (sub >> 1) * 8;
    const u32 baseQh = smem_u32(sQh);
    u32 qfh[4][4];
    #pragma unroll
    for (int ks = 0; ks < 4; ks++) {
        u32 off = (u32)(((wm + arow) * KPITCH + ks * 16 + acol) * 2);
        ldsm_x4(qfh[ks], baseQh + off);
    }

    const int g = lane >> 2, t4 = lane & 3;
    const int row_g0 = q0 + wm + g;
    const int row_g1 = row_g0 + 8;
    const float bq0 = gbq[(size_t)bh * T_ + row_g0];
    const float bq1 = gbq[(size_t)bh * T_ + row_g1];

    float m0 = -INFINITY, m1 = -INFINITY, l0 = 0.f, l1 = 0.f;
    float o[8][4];
    #pragma unroll
    for (int j = 0; j < 8; j++)
        #pragma unroll
        for (int e = 0; e < 4; e++) o[j][e] = 0.f;

    const int brow = lane & 7;
    const int bcol = ((lane >> 3) & 1) * 8;
    const int vrow = lane & 15;

    for (int kt = 0; kt < ktmax; kt++) {
        const int s = kt & 1;
        const int k0 = kt * 64;

        CP_WAIT(0);
        __syncthreads();
        if (kt + 1 < ktmax) { LOAD_TILE(kt + 1, 1 - s); CP_COMMIT(); }

        const u32 bK = kvb + s * (2 * APL);
        const u32 bV = bK + APL;
        const float* kp_s = skp + s * 64;

        float s_[8][4];
        #pragma unroll
        for (int j = 0; j < 8; j++)
            #pragma unroll
            for (int e = 0; e < 4; e++) s_[j][e] = 0.f;

        #pragma unroll
        for (int ks = 0; ks < 4; ks++) {
            #pragma unroll
            for (int j = 0; j < 8; j++) {
                u32 kf[2];
                const u32 off = (u32)(((j * 8 + brow) * KPITCH + ks * 16 + bcol) * 2);
                ldsm_x2(kf, bK + off);
                mma_f16(s_[j], qfh[ks], kf);
            }
        }

        const bool need_mask = (kt >= 2 * qi);
        #pragma unroll
        for (int j = 0; j < 8; j++) {
            const float2 kp = *(const float2*)&kp_s[j * 8 + 2 * t4];
            s_[j][0] = s_[j][0] * SCALE_ + bq0 * kp.x;
            s_[j][1] = s_[j][1] * SCALE_ + bq0 * kp.y;
            s_[j][2] = s_[j][2] * SCALE_ + bq1 * kp.x;
            s_[j][3] = s_[j][3] * SCALE_ + bq1 * kp.y;
            if (need_mask) {
                const int key0 = k0 + j * 8 + 2 * t4;
                if (key0 > row_g0)     s_[j][0] = -INFINITY;
                if (key0 + 1 > row_g0) s_[j][1] = -INFINITY;
                if (key0 > row_g1)     s_[j][2] = -INFINITY;
                if (key0 + 1 > row_g1) s_[j][3] = -INFINITY;
            }
        }

        float mx0 = s_[0][0], mx1 = s_[0][2];
        #pragma unroll
        for (int j = 0; j < 8; j++) {
            mx0 = fmaxf(mx0, fmaxf(s_[j][0], s_[j][1]));
            mx1 = fmaxf(mx1, fmaxf(s_[j][2], s_[j][3]));
        }
        mx0 = fmaxf(mx0, __shfl_xor_sync(0xffffffffu, mx0, 1));
        mx0 = fmaxf(mx0, __shfl_xor_sync(0xffffffffu, mx0, 2));
        mx1 = fmaxf(mx1, __shfl_xor_sync(0xffffffffu, mx1, 1));
        mx1 = fmaxf(mx1, __shfl_xor_sync(0xffffffffu, mx1, 2));

        const float mn0 = fmaxf(m0, mx0), mn1 = fmaxf(m1, mx1);
        const float a0 = __expf(m0 - mn0), a1 = __expf(m1 - mn1);
        m0 = mn0; m1 = mn1;

        float rs0 = 0.f, rs1 = 0.f;
        #pragma unroll
        for (int j = 0; j < 8; j++) {
            s_[j][0] = __expf(s_[j][0] - m0);
            s_[j][1] = __expf(s_[j][1] - m0);
            s_[j][2] = __expf(s_[j][2] - m1);
            s_[j][3] = __expf(s_[j][3] - m1);
            rs0 += s_[j][0] + s_[j][1];
            rs1 += s_[j][2] + s_[j][3];
        }
        rs0 += __shfl_xor_sync(0xffffffffu, rs0, 1);
        rs0 += __shfl_xor_sync(0xffffffffu, rs0, 2);
        rs1 += __shfl_xor_sync(0xffffffffu, rs1, 1);
        rs1 += __shfl_xor_sync(0xffffffffu, rs1, 2);
        l0 = l0 * a0 + rs0;
        l1 = l1 * a1 + rs1;

        #pragma unroll
        for (int j = 0; j < 8; j++) {
            o[j][0] *= a0; o[j][1] *= a0;
            o[j][2] *= a1; o[j][3] *= a1;
        }

        // P fragments: single fp16 rounding (lo dropped)
        u32 pah[4][4];
        #pragma unroll
        for (int s2 = 0; s2 < 4; s2++) {
            pah[s2][0] = pack2h(s_[2 * s2][0],     s_[2 * s2][1]);
            pah[s2][1] = pack2h(s_[2 * s2][2],     s_[2 * s2][3]);
            pah[s2][2] = pack2h(s_[2 * s2 + 1][0], s_[2 * s2 + 1][1]);
            pah[s2][3] = pack2h(s_[2 * s2 + 1][2], s_[2 * s2 + 1][3]);
        }

        #pragma unroll
        for (int s2 = 0; s2 < 4; s2++) {
            #pragma unroll
            for (int j = 0; j < 8; j++) {
                u32 vf[2];
                const u32 off = (u32)(((s2 * 16 + vrow) * KPITCH + j * 8) * 2);
                ldsm_x2t(vf, bV + off);
                mma_f16(o[j], pah[s2], vf);
            }
        }
    }
    #undef LOAD_TILE

    const float inv0 = 1.f / l0, inv1 = 1.f / l1;
    #pragma unroll
    for (int j = 0; j < 8; j++) {
        const u32 h01 = pack2h(o[j][0] * inv0, o[j][1] * inv0);
        const u32 h23 = pack2h(o[j][2] * inv1, o[j][3] * inv1);
        const size_t r0o = (size_t)(b * T_ + row_g0) * C_ + h * HD_ + j * 8 + 2 * t4;
        const size_t r1o = (size_t)(b * T_ + row_g1) * C_ + h * HD_ + j * 8 + 2 * t4;
        *(u32*)&atth[r0o] = h01;
        *(u32*)&atth[r1o] = h23;
    }
}

// ---------------------------------------------------------------------------
extern "C" void kernel_launch(void* const* d_in, const int* in_sizes, int n_in,
                              void* d_out, int out_size)
{
    const float* x           = (const float*)d_in[0];
    const float* w_qkv       = (const float*)d_in[1];
    const float* w_out       = (const float*)d_in[2];
    const float* head_scales = (const float*)d_in[3];
    const float* head_dirs   = (const float*)d_in[4];
    float*       out         = (float*)d_out;

    hf *xh, *qkvh, *qkvl, *ah, *wq, *wo;
    float *bq, *kp;
    cudaGetSymbolAddress((void**)&xh, g_xh);
    cudaGetSymbolAddress((void**)&qkvh, g_qkvh);
    cudaGetSymbolAddress((void**)&qkvl, g_qkvl);
    cudaGetSymbolAddress((void**)&ah, g_ah);
    cudaGetSymbolAddress((void**)&wq, g_wq);
    cudaGetSymbolAddress((void**)&wo, g_wo);
    cudaGetSymbolAddress((void**)&bq, g_bq);
    cudaGetSymbolAddress((void**)&kp, g_kp);

    const int ATT_SMEM = (128 + 64 * 4) * KPITCH * (int)sizeof(hf)
                       + 2 * 64 * (int)sizeof(float);
    cudaFuncSetAttribute(attn_mma, cudaFuncAttributeMaxDynamicSharedMemorySize, ATT_SMEM);
    cudaFuncSetAttribute((const void*)gemm_f16<true>,
                         cudaFuncAttributeMaxDynamicSharedMemorySize, GSMEM_TOTAL);
    cudaFuncSetAttribute((const void*)gemm_f16<false>,
                         cudaFuncAttributeMaxDynamicSharedMemorySize, GSMEM_TOTAL);

    // converts
    {
        int n4 = BT_ * C_ / 4;
        cvt_kernel<<<(n4 + 255) / 256, 256>>>(x, xh, n4);
    }
    {
        dim3 grid(3 * C_ / 32, C_ / 32), blk(32, 8);
        cvt_transpose_kernel<<<grid, blk>>>(w_qkv, wq, C_, 3 * C_);
    }
    {
        dim3 grid(C_ / 32, C_ / 32), blk(32, 8);
        cvt_transpose_kernel<<<grid, blk>>>(w_out, wo, C_, C_);
    }

    // 1) qkv = x_hi @ w_hi (split hi/lo output for proj precision)
    {
        dim3 grid(3 * C_ / BN, BT_ / BM);
        gemm_f16<true><<<grid, 256, GSMEM_TOTAL>>>(
            xh, wq, nullptr, qkvh, qkvl, BT_, 3 * C_, C_);
    }
    // 1b) E8 projections
    {
        proj_kernel<<<(BT_ * H_) / 256, 256>>>(qkvh, qkvl, head_scales, head_dirs, bq, kp);
    }
    // 2) attention (hi-only output)
    {
        dim3 grid(T_ / 128, B_ * H_);
        attn_mma<<<grid, 256, ATT_SMEM>>>(qkvh, bq, kp, ah);
    }
    // 3) out = att_hi @ w_hi (fp32 output)
    {
        dim3 grid(C_ / BN, BT_ / BM);
        gemm_f16<false><<<grid, 256, GSMEM_TOTAL>>>(
            ah, wo, out, nullptr, nullptr, BT_, C_, C_);
    }
}